// round 1
// baseline (speedup 1.0000x reference)
#include <cuda_runtime.h>
#include <math.h>
#include <stdint.h>

#define DIMX    2048
#define HEADS   16
#define DH      128
#define AINNER  2048      // HEADS*DH
#define FFI     8192
#define FUSEDW  18688     // AINNER + 2*DH + 2*FFI
#define SEQ     2048
#define NROWS   4096      // B*N

// ---------------- scratch (static device, no allocs) ----------------
static __device__ float g_h[(size_t)NROWS * DIMX];       //  33.5 MB
static __device__ float g_proj[(size_t)NROWS * FUSEDW];  // 306   MB
static __device__ float g_attn[(size_t)NROWS * AINNER];  //  33.5 MB

// ---------------- LayerNorm ----------------
__global__ void ln_kernel(const float* __restrict__ x,
                          const float* __restrict__ gamma,
                          const float* __restrict__ beta) {
    int r = blockIdx.x;
    const float* xr = x + (size_t)r * DIMX;
    float s = 0.f, s2 = 0.f;
    for (int i = threadIdx.x; i < DIMX; i += 256) {
        float v = xr[i]; s += v; s2 += v * v;
    }
    #pragma unroll
    for (int m = 16; m; m >>= 1) {
        s  += __shfl_xor_sync(0xffffffffu, s,  m);
        s2 += __shfl_xor_sync(0xffffffffu, s2, m);
    }
    __shared__ float red0[8], red1[8];
    int w = threadIdx.x >> 5, l = threadIdx.x & 31;
    if (l == 0) { red0[w] = s; red1[w] = s2; }
    __syncthreads();
    __shared__ float smu, srstd;
    if (threadIdx.x == 0) {
        float a = 0.f, b2 = 0.f;
        #pragma unroll
        for (int i = 0; i < 8; i++) { a += red0[i]; b2 += red1[i]; }
        float mu  = a / DIMX;
        float var = b2 / DIMX - mu * mu;
        smu = mu; srstd = 1.0f / sqrtf(var + 1e-5f);
    }
    __syncthreads();
    float mu = smu, rstd = srstd;
    float* hr = g_h + (size_t)r * DIMX;
    for (int i = threadIdx.x; i < DIMX; i += 256)
        hr[i] = (xr[i] - mu) * rstd * gamma[i] + beta[i];
}

// ---------------- generic dual-phase SGEMM: C = A1@B1 + A2@B2 ----------------
#define BM 128
#define BN 128
#define BK 16
#define APAD 4

__global__ __launch_bounds__(256, 2)
void gemm_dual(const float* __restrict__ A1, int lda1, const float* __restrict__ B1, int K1,
               const float* __restrict__ A2, int lda2, const float* __restrict__ B2, int K2,
               float* __restrict__ C, int N) {
    __shared__ float As[BK][BM + APAD];
    __shared__ float Bs[BK][BN];
    int tid = threadIdx.x;
    int m0 = blockIdx.x * BM;   // M tiles fastest -> streamed B panel read ~once from HBM
    int n0 = blockIdx.y * BN;
    int tm = (tid >> 4) << 3;
    int tn = (tid & 15) << 3;
    float acc[8][8];
    #pragma unroll
    for (int i = 0; i < 8; i++)
        #pragma unroll
        for (int j = 0; j < 8; j++) acc[i][j] = 0.f;

    #pragma unroll 1
    for (int phase = 0; phase < 2; ++phase) {
        const float* A = phase ? A2 : A1;
        const float* B = phase ? B2 : B1;
        int K   = phase ? K2  : K1;
        int lda = phase ? lda2 : lda1;
        #pragma unroll 1
        for (int k0 = 0; k0 < K; k0 += BK) {
            #pragma unroll
            for (int it = 0; it < 2; ++it) {
                int lidx = tid + it * 256;
                int row = lidx >> 2;
                int c4  = (lidx & 3) << 2;
                float4 v = *(const float4*)(A + (size_t)(m0 + row) * lda + k0 + c4);
                As[c4 + 0][row] = v.x; As[c4 + 1][row] = v.y;
                As[c4 + 2][row] = v.z; As[c4 + 3][row] = v.w;
            }
            #pragma unroll
            for (int it = 0; it < 2; ++it) {
                int lidx = tid + it * 256;
                int row = lidx >> 5;
                int c4  = (lidx & 31) << 2;
                *(float4*)(&Bs[row][c4]) =
                    *(const float4*)(B + (size_t)(k0 + row) * N + n0 + c4);
            }
            __syncthreads();
            #pragma unroll
            for (int k = 0; k < BK; k++) {
                float a[8], b[8];
                *(float4*)(a)     = *(const float4*)(&As[k][tm]);
                *(float4*)(a + 4) = *(const float4*)(&As[k][tm + 4]);
                *(float4*)(b)     = *(const float4*)(&Bs[k][tn]);
                *(float4*)(b + 4) = *(const float4*)(&Bs[k][tn + 4]);
                #pragma unroll
                for (int i = 0; i < 8; i++)
                    #pragma unroll
                    for (int j = 0; j < 8; j++)
                        acc[i][j] += a[i] * b[j];
            }
            __syncthreads();
        }
    }
    #pragma unroll
    for (int i = 0; i < 8; i++) {
        float* cp = C + (size_t)(m0 + tm + i) * N + n0 + tn;
        *(float4*)(cp)     = make_float4(acc[i][0], acc[i][1], acc[i][2], acc[i][3]);
        *(float4*)(cp + 4) = make_float4(acc[i][4], acc[i][5], acc[i][6], acc[i][7]);
    }
}

// ---------------- RoPE in place on q (cols 0..2048) and k (cols 2048..2176) ----------------
__global__ void rope_kernel() {
    int r = blockIdx.x;
    int n = r & (SEQ - 1);
    float* row = g_proj + (size_t)r * FUSEDW;
    for (int idx = threadIdx.x; idx < HEADS * 64 + 64; idx += blockDim.x) {
        int d, c0;
        if (idx < HEADS * 64) { int head = idx >> 6; d = idx & 63; c0 = head * DH + d; }
        else                  { d = idx - HEADS * 64; c0 = AINNER + d; }
        double invf_d = pow(10000.0, -(double)d / 64.0);
        float  invf   = (float)invf_d;
        // match reference: theta rounded to f32, then accurate sin/cos of that value
        float theta = (float)((double)n * (double)invf);
        float c = (float)cos((double)theta);
        float s = (float)sin((double)theta);
        float t0 = row[c0], t1 = row[c0 + 64];
        row[c0]      = t0 * c - t1 * s;
        row[c0 + 64] = t1 * c + t0 * s;
    }
}

// ---------------- flash attention (MQA, causal) ----------------
#define QT 64
#define KT 64
#define KSTR 132
#define PSTR 68
#define FA_SMEM ((3 * QT * KSTR + QT * PSTR) * 4)

extern __shared__ float fa_smem[];
__global__ __launch_bounds__(256)
void attn_kernel() {
    float* q_sm = fa_smem;
    float* k_sm = q_sm + QT * KSTR;
    float* v_sm = k_sm + KT * KSTR;
    float* p_sm = v_sm + KT * KSTR;
    int tid = threadIdx.x;
    int qt = blockIdx.x;
    int bh = blockIdx.y;
    int b = bh >> 4, h = bh & 15;
    size_t rowbase = (size_t)(b * SEQ + qt * QT);

    for (int lidx = tid; lidx < QT * 32; lidx += 256) {
        int i = lidx >> 5; int d4 = (lidx & 31) << 2;
        *(float4*)(q_sm + i * KSTR + d4) =
            *(const float4*)(g_proj + (rowbase + i) * FUSEDW + h * DH + d4);
    }
    int ty = tid >> 4, tx = tid & 15;
    float m_i[4], l_i[4], accO[4][8];
    #pragma unroll
    for (int i = 0; i < 4; i++) {
        m_i[i] = -INFINITY; l_i[i] = 0.f;
        #pragma unroll
        for (int j = 0; j < 8; j++) accO[i][j] = 0.f;
    }
    const float scale = 0.08838834764831845f;  // 1/sqrt(128)

    for (int jt = 0; jt <= qt; ++jt) {
        __syncthreads();  // protect k/v/p smem from previous iteration
        size_t krow = (size_t)(b * SEQ + jt * KT);
        for (int lidx = tid; lidx < KT * 32; lidx += 256) {
            int i = lidx >> 5; int d4 = (lidx & 31) << 2;
            // layout per row: q[0..2048) | k[2048..2176) | v[2176..2304) | ff
            const float* src = g_proj + (krow + i) * FUSEDW + AINNER + d4;
            *(float4*)(k_sm + i * KSTR + d4) = *(const float4*)(src);       // k
            *(float4*)(v_sm + i * KSTR + d4) = *(const float4*)(src + DH);  // v
        }
        __syncthreads();
        // --- S = Q K^T ---
        float s[4][4];
        #pragma unroll
        for (int i = 0; i < 4; i++)
            #pragma unroll
            for (int j = 0; j < 4; j++) s[i][j] = 0.f;
        for (int d4 = 0; d4 < DH; d4 += 4) {
            float4 qv[4], kv[4];
            #pragma unroll
            for (int i = 0; i < 4; i++) qv[i] = *(const float4*)(q_sm + (ty * 4 + i) * KSTR + d4);
            #pragma unroll
            for (int j = 0; j < 4; j++) kv[j] = *(const float4*)(k_sm + (tx * 4 + j) * KSTR + d4);
            #pragma unroll
            for (int i = 0; i < 4; i++)
                #pragma unroll
                for (int j = 0; j < 4; j++)
                    s[i][j] += qv[i].x * kv[j].x + qv[i].y * kv[j].y +
                               qv[i].z * kv[j].z + qv[i].w * kv[j].w;
        }
        float alpha[4];
        #pragma unroll
        for (int i = 0; i < 4; i++) {
            int qi = ty * 4 + i;
            float mx = -INFINITY;
            #pragma unroll
            for (int j = 0; j < 4; j++) {
                s[i][j] *= scale;
                if (jt == qt && (tx * 4 + j) > qi) s[i][j] = -INFINITY;
                mx = fmaxf(mx, s[i][j]);
            }
            #pragma unroll
            for (int msk = 8; msk; msk >>= 1)
                mx = fmaxf(mx, __shfl_xor_sync(0xffffffffu, mx, msk));
            float mnew = fmaxf(m_i[i], mx);
            float su = 0.f;
            #pragma unroll
            for (int j = 0; j < 4; j++) {
                float p = expf(s[i][j] - mnew);
                p_sm[qi * PSTR + tx * 4 + j] = p;
                su += p;
            }
            #pragma unroll
            for (int msk = 8; msk; msk >>= 1)
                su += __shfl_xor_sync(0xffffffffu, su, msk);
            alpha[i] = expf(m_i[i] - mnew);
            l_i[i] = l_i[i] * alpha[i] + su;
            m_i[i] = mnew;
        }
        __syncthreads();
        #pragma unroll
        for (int i = 0; i < 4; i++)
            #pragma unroll
            for (int j = 0; j < 8; j++) accO[i][j] *= alpha[i];
        for (int j = 0; j < KT; j++) {
            float4 v0 = *(const float4*)(v_sm + j * KSTR + tx * 8);
            float4 v1 = *(const float4*)(v_sm + j * KSTR + tx * 8 + 4);
            #pragma unroll
            for (int i = 0; i < 4; i++) {
                float p = p_sm[(ty * 4 + i) * PSTR + j];
                accO[i][0] += p * v0.x; accO[i][1] += p * v0.y;
                accO[i][2] += p * v0.z; accO[i][3] += p * v0.w;
                accO[i][4] += p * v1.x; accO[i][5] += p * v1.y;
                accO[i][6] += p * v1.z; accO[i][7] += p * v1.w;
            }
        }
    }
    #pragma unroll
    for (int i = 0; i < 4; i++) {
        float inv = 1.0f / l_i[i];
        float* op = g_attn + (rowbase + ty * 4 + i) * AINNER + h * DH + tx * 8;
        *(float4*)(op)     = make_float4(accO[i][0] * inv, accO[i][1] * inv,
                                         accO[i][2] * inv, accO[i][3] * inv);
        *(float4*)(op + 4) = make_float4(accO[i][4] * inv, accO[i][5] * inv,
                                         accO[i][6] * inv, accO[i][7] * inv);
    }
}

// ---------------- SwiGLU (in place into x_ff region) ----------------
__global__ void swiglu_kernel() {
    int idx = blockIdx.x * 256 + threadIdx.x;       // one float4 each
    int r  = idx >> 11;                             // FFI/4 = 2048 float4 per row
    int c4 = (idx & 2047) << 2;
    float* base = g_proj + (size_t)r * FUSEDW + (AINNER + 2 * DH);
    float4 xv = *(const float4*)(base + c4);
    float4 gv = *(const float4*)(base + FFI + c4);
    float4 o;
    o.x = xv.x * (gv.x / (1.f + expf(-gv.x)));
    o.y = xv.y * (gv.y / (1.f + expf(-gv.y)));
    o.z = xv.z * (gv.z / (1.f + expf(-gv.z)));
    o.w = xv.w * (gv.w / (1.f + expf(-gv.w)));
    *(float4*)(base + c4) = o;
}

// ---------------- launch ----------------
extern "C" void kernel_launch(void* const* d_in, const int* in_sizes, int n_in,
                              void* d_out, int out_size) {
    const float* x          = (const float*)d_in[0];
    const float* gamma      = (const float*)d_in[1];
    const float* beta       = (const float*)d_in[2];
    const float* w_fused    = (const float*)d_in[3];
    const float* w_attn_out = (const float*)d_in[4];
    const float* w_ff_out   = (const float*)d_in[5];
    float* out = (float*)d_out;

    void *p_h, *p_proj, *p_attn;
    cudaGetSymbolAddress(&p_h, g_h);
    cudaGetSymbolAddress(&p_proj, g_proj);
    cudaGetSymbolAddress(&p_attn, g_attn);
    float* gh = (float*)p_h;
    float* gp = (float*)p_proj;
    float* ga = (float*)p_attn;

    cudaFuncSetAttribute(attn_kernel, cudaFuncAttributeMaxDynamicSharedMemorySize, FA_SMEM);

    ln_kernel<<<NROWS, 256>>>(x, gamma, beta);

    gemm_dual<<<dim3(NROWS / BM, FUSEDW / BN), 256>>>(
        gh, DIMX, w_fused, DIMX,
        nullptr, 0, nullptr, 0,
        gp, FUSEDW);

    rope_kernel<<<NROWS, 256>>>();

    attn_kernel<<<dim3(SEQ / QT, 2 * HEADS), 256, FA_SMEM>>>();

    swiglu_kernel<<<(NROWS * (FFI / 4)) / 256, 256>>>();

    gemm_dual<<<dim3(NROWS / BM, DIMX / BN), 256>>>(
        ga, AINNER, w_attn_out, AINNER,
        gp + (AINNER + 2 * DH), FUSEDW, w_ff_out, FFI,
        out, DIMX);
}

// round 3
// speedup vs baseline: 1.6910x; 1.6910x over previous
#include <cuda_runtime.h>
#include <cuda_bf16.h>
#include <math.h>
#include <stdint.h>

#define DIMX    2048
#define HEADS   16
#define DH      128
#define AINNER  2048      // HEADS*DH
#define FFI     8192
#define FUSEDW  18688     // AINNER + 2*DH + 2*FFI
#define SEQ     2048
#define NROWS   4096      // B*N

// ======================= scratch (static device) =======================
static __device__ float g_proj[(size_t)NROWS * FUSEDW];  // 306 MB
static __device__ float g_attn[(size_t)NROWS * AINNER];  //  33.5 MB
static __device__ __nv_bfloat16 g_h_hi[(size_t)NROWS * DIMX],   g_h_lo[(size_t)NROWS * DIMX];
static __device__ __nv_bfloat16 g_wf_h[(size_t)FUSEDW * DIMX],  g_wf_l[(size_t)FUSEDW * DIMX];
static __device__ __nv_bfloat16 g_wa_h[(size_t)DIMX * AINNER],  g_wa_l[(size_t)DIMX * AINNER];
static __device__ __nv_bfloat16 g_wo_h[(size_t)DIMX * FFI],     g_wo_l[(size_t)DIMX * FFI];
static __device__ __nv_bfloat16 g_at_h[(size_t)NROWS * AINNER], g_at_l[(size_t)NROWS * AINNER];
static __device__ __nv_bfloat16 g_ff_h[(size_t)NROWS * FFI],    g_ff_l[(size_t)NROWS * FFI];

__device__ __forceinline__ void split2(float v, __nv_bfloat16* H, __nv_bfloat16* L, size_t o) {
    __nv_bfloat16 h = __float2bfloat16(v);
    H[o] = h;
    L[o] = __float2bfloat16(v - __bfloat162float(h));
}

__device__ __forceinline__ uint32_t smem_u32(const void* p) {
    uint32_t a;
    asm("{ .reg .u64 t; cvta.to.shared.u64 t, %1; cvt.u32.u64 %0, t; }" : "=r"(a) : "l"(p));
    return a;
}
__device__ __forceinline__ void ldmx4(uint32_t* r, uint32_t addr) {
    asm volatile("ldmatrix.sync.aligned.m8n8.x4.shared.b16 {%0,%1,%2,%3}, [%4];"
                 : "=r"(r[0]), "=r"(r[1]), "=r"(r[2]), "=r"(r[3]) : "r"(addr));
}
__device__ __forceinline__ void mma_bf16(float* c, const uint32_t* a, uint32_t b0, uint32_t b1) {
    asm volatile(
        "mma.sync.aligned.m16n8k16.row.col.f32.bf16.bf16.f32 "
        "{%0,%1,%2,%3}, {%4,%5,%6,%7}, {%8,%9}, {%0,%1,%2,%3};"
        : "+f"(c[0]), "+f"(c[1]), "+f"(c[2]), "+f"(c[3])
        : "r"(a[0]), "r"(a[1]), "r"(a[2]), "r"(a[3]), "r"(b0), "r"(b1));
}
#define CP_ASYNC16(sa, ga) \
    asm volatile("cp.async.cg.shared.global [%0], [%1], 16;" :: "r"(sa), "l"(ga))
#define CP_COMMIT()  asm volatile("cp.async.commit_group;" ::: "memory")
#define CP_WAIT1()   asm volatile("cp.async.wait_group 1;" ::: "memory")

// ======================= LayerNorm -> bf16 split =======================
__global__ void ln_split_kernel(const float* __restrict__ x,
                                const float* __restrict__ gamma,
                                const float* __restrict__ beta) {
    int r = blockIdx.x;
    const float* xr = x + (size_t)r * DIMX;
    float s = 0.f, s2 = 0.f;
    for (int i = threadIdx.x; i < DIMX; i += 256) {
        float v = xr[i]; s += v; s2 += v * v;
    }
    #pragma unroll
    for (int m = 16; m; m >>= 1) {
        s  += __shfl_xor_sync(0xffffffffu, s,  m);
        s2 += __shfl_xor_sync(0xffffffffu, s2, m);
    }
    __shared__ float red0[8], red1[8];
    int w = threadIdx.x >> 5, l = threadIdx.x & 31;
    if (l == 0) { red0[w] = s; red1[w] = s2; }
    __syncthreads();
    __shared__ float smu, srstd;
    if (threadIdx.x == 0) {
        float a = 0.f, b2 = 0.f;
        #pragma unroll
        for (int i = 0; i < 8; i++) { a += red0[i]; b2 += red1[i]; }
        float mu  = a / DIMX;
        float var = b2 / DIMX - mu * mu;
        smu = mu; srstd = 1.0f / sqrtf(var + 1e-5f);
    }
    __syncthreads();
    float mu = smu, rstd = srstd;
    for (int i = threadIdx.x; i < DIMX; i += 256) {
        float v = (xr[i] - mu) * rstd * gamma[i] + beta[i];
        split2(v, g_h_hi, g_h_lo, (size_t)r * DIMX + i);
    }
}

// ======================= transpose + split: W[K,N] -> T[N,K] bf16 hi/lo =======================
__global__ void transpose_split(const float* __restrict__ W, int K, int N,
                                __nv_bfloat16* __restrict__ Th, __nv_bfloat16* __restrict__ Tl) {
    __shared__ float t[32][33];
    int n0 = blockIdx.x * 32, k0 = blockIdx.y * 32;
    int tx = threadIdx.x, ty = threadIdx.y;
    for (int j = ty; j < 32; j += 8)
        t[j][tx] = W[(size_t)(k0 + j) * N + n0 + tx];
    __syncthreads();
    for (int j = ty; j < 32; j += 8) {
        float v = t[tx][j];                    // = W[k0+tx][n0+j]
        split2(v, Th, Tl, (size_t)(n0 + j) * K + k0 + tx);
    }
}

// ======================= flat fp32 -> bf16 split =======================
__global__ void split_flat(const float* __restrict__ src,
                           __nv_bfloat16* __restrict__ H, __nv_bfloat16* __restrict__ L) {
    size_t i4 = ((size_t)blockIdx.x * 256 + threadIdx.x) * 4;
    float4 v = *(const float4*)(src + i4);
    split2(v.x, H, L, i4 + 0);
    split2(v.y, H, L, i4 + 1);
    split2(v.z, H, L, i4 + 2);
    split2(v.w, H, L, i4 + 3);
}

// ======================= mma.sync dual-phase GEMM =======================
// C[M, ldc] = A1@B1^T + A2@B2^T.  All operands K-major bf16 hi/lo pairs.
// Tile 128x128, BK=32, 256 threads (8 warps: warp tile 32Mx64N), cp.async 2-stage.
#define BKC 32
#define ASTRIDE 80                     // 64B data + 16B pad per row (conflict-free LDSM)
#define MAT_BYTES (128 * ASTRIDE)      // 10240
#define STAGE_BYTES (4 * MAT_BYTES)    // 40960 (Ah, Al, Bh, Bl)
#define GEMM_SMEM (2 * STAGE_BYTES)    // 81920

__global__ __launch_bounds__(256, 1)
void gemm_tc(const __nv_bfloat16* __restrict__ Ah1, const __nv_bfloat16* __restrict__ Al1,
             const __nv_bfloat16* __restrict__ Bh1, const __nv_bfloat16* __restrict__ Bl1, int K1,
             const __nv_bfloat16* __restrict__ Ah2, const __nv_bfloat16* __restrict__ Al2,
             const __nv_bfloat16* __restrict__ Bh2, const __nv_bfloat16* __restrict__ Bl2, int K2,
             float* __restrict__ C, int ldc) {
    extern __shared__ char smem[];
    uint32_t smb = smem_u32(smem);
    int tid = threadIdx.x;
    int w = tid >> 5, l = tid & 31;
    int wm = w & 3, wn = w >> 2;               // warp tile: rows wm*32.. , cols wn*64..
    int m0 = blockIdx.x * 128;
    int n0 = blockIdx.y * 128;
    int S1 = K1 / BKC, S2 = K2 / BKC, S = S1 + S2;

    float acc[2][8][4];
    #pragma unroll
    for (int t = 0; t < 2; t++)
        #pragma unroll
        for (int n = 0; n < 8; n++)
            #pragma unroll
            for (int j = 0; j < 4; j++) acc[t][n][j] = 0.f;

    auto issue = [&](int s) {
        const __nv_bfloat16 *ah, *al, *bh, *bl; int K, k0;
        if (s < S1) { ah = Ah1; al = Al1; bh = Bh1; bl = Bl1; K = K1; k0 = s * BKC; }
        else        { ah = Ah2; al = Al2; bh = Bh2; bl = Bl2; K = K2; k0 = (s - S1) * BKC; }
        uint32_t sb0 = smb + (s & 1) * STAGE_BYTES;
        #pragma unroll
        for (int t = 0; t < 8; t++) {
            int q = tid + (t << 8);            // 0..2047
            int mat = q >> 9;                  // 0..3
            int rem = q & 511;
            int row = rem >> 2;                // 0..127
            int c   = rem & 3;                 // 16B chunk within row
            const __nv_bfloat16* g = (mat == 0) ? ah : (mat == 1) ? al : (mat == 2) ? bh : bl;
            int rb = (mat < 2) ? m0 : n0;
            const __nv_bfloat16* gp = g + (size_t)(rb + row) * K + k0 + c * 8;
            uint32_t sa = sb0 + mat * MAT_BYTES + row * ASTRIDE + c * 16;
            CP_ASYNC16(sa, gp);
        }
        CP_COMMIT();
    };

    issue(0);
    for (int s = 0; s < S; ++s) {
        if (s + 1 < S) issue(s + 1);
        else CP_COMMIT();                      // empty group keeps wait-count uniform
        CP_WAIT1();
        __syncthreads();

        uint32_t sA = smb + (s & 1) * STAGE_BYTES;
        uint32_t sB = sA + 2 * MAT_BYTES;
        #pragma unroll
        for (int kk = 0; kk < BKC; kk += 16) {
            uint32_t ahf[2][4], alf[2][4];
            #pragma unroll
            for (int t = 0; t < 2; t++) {
                uint32_t ro = (uint32_t)((wm * 32 + t * 16 + ((l >> 3) & 1) * 8 + (l & 7)) * ASTRIDE
                                         + ((kk >> 3) + (l >> 4)) * 16);
                ldmx4(ahf[t], sA + ro);
                ldmx4(alf[t], sA + MAT_BYTES + ro);
            }
            #pragma unroll
            for (int u = 0; u < 4; u++) {
                uint32_t bo = (uint32_t)((wn * 64 + u * 16 + (l >> 4) * 8 + (l & 7)) * ASTRIDE
                                         + ((kk >> 3) + ((l >> 3) & 1)) * 16);
                uint32_t bhf[4], blf[4];
                ldmx4(bhf, sB + bo);
                ldmx4(blf, sB + MAT_BYTES + bo);
                #pragma unroll
                for (int t = 0; t < 2; t++) {
                    #pragma unroll
                    for (int h = 0; h < 2; h++) {
                        float* c = acc[t][u * 2 + h];
                        mma_bf16(c, ahf[t], bhf[h * 2], bhf[h * 2 + 1]);
                        mma_bf16(c, ahf[t], blf[h * 2], blf[h * 2 + 1]);
                        mma_bf16(c, alf[t], bhf[h * 2], bhf[h * 2 + 1]);
                    }
                }
            }
        }
        __syncthreads();
    }

    #pragma unroll
    for (int t = 0; t < 2; t++) {
        int row = m0 + wm * 32 + t * 16 + (l >> 2);
        #pragma unroll
        for (int n = 0; n < 8; n++) {
            int col = n0 + wn * 64 + n * 8 + (l & 3) * 2;
            *(float2*)(C + (size_t)row * ldc + col)       = make_float2(acc[t][n][0], acc[t][n][1]);
            *(float2*)(C + (size_t)(row + 8) * ldc + col) = make_float2(acc[t][n][2], acc[t][n][3]);
        }
    }
}

// ======================= RoPE in place on q/k of g_proj =======================
__global__ void rope_kernel() {
    int r = blockIdx.x;
    int n = r & (SEQ - 1);
    float* row = g_proj + (size_t)r * FUSEDW;
    for (int idx = threadIdx.x; idx < HEADS * 64 + 64; idx += blockDim.x) {
        int d, c0;
        if (idx < HEADS * 64) { int head = idx >> 6; d = idx & 63; c0 = head * DH + d; }
        else                  { d = idx - HEADS * 64; c0 = AINNER + d; }
        double invf_d = pow(10000.0, -(double)d / 64.0);
        float  invf   = (float)invf_d;
        float theta = (float)((double)n * (double)invf);
        float c = (float)cos((double)theta);
        float s = (float)sin((double)theta);
        float t0 = row[c0], t1 = row[c0 + 64];
        row[c0]      = t0 * c - t1 * s;
        row[c0 + 64] = t1 * c + t0 * s;
    }
}

// ======================= flash attention (MQA, causal) =======================
#define QT 64
#define KT 64
#define KSTR 132
#define PSTR 68
#define FA_SMEM ((3 * QT * KSTR + QT * PSTR) * 4)

extern __shared__ float fa_smem[];
__global__ __launch_bounds__(256)
void attn_kernel() {
    float* q_sm = fa_smem;
    float* k_sm = q_sm + QT * KSTR;
    float* v_sm = k_sm + KT * KSTR;
    float* p_sm = v_sm + KT * KSTR;
    int tid = threadIdx.x;
    int qt = blockIdx.x;
    int bh = blockIdx.y;
    int b = bh >> 4, h = bh & 15;
    size_t rowbase = (size_t)(b * SEQ + qt * QT);

    for (int lidx = tid; lidx < QT * 32; lidx += 256) {
        int i = lidx >> 5; int d4 = (lidx & 31) << 2;
        *(float4*)(q_sm + i * KSTR + d4) =
            *(const float4*)(g_proj + (rowbase + i) * FUSEDW + h * DH + d4);
    }
    int ty = tid >> 4, tx = tid & 15;
    float m_i[4], l_i[4], accO[4][8];
    #pragma unroll
    for (int i = 0; i < 4; i++) {
        m_i[i] = -INFINITY; l_i[i] = 0.f;
        #pragma unroll
        for (int j = 0; j < 8; j++) accO[i][j] = 0.f;
    }
    const float scale = 0.08838834764831845f;

    for (int jt = 0; jt <= qt; ++jt) {
        __syncthreads();
        size_t krow = (size_t)(b * SEQ + jt * KT);
        for (int lidx = tid; lidx < KT * 32; lidx += 256) {
            int i = lidx >> 5; int d4 = (lidx & 31) << 2;
            const float* src = g_proj + (krow + i) * FUSEDW + AINNER + d4;
            *(float4*)(k_sm + i * KSTR + d4) = *(const float4*)(src);
            *(float4*)(v_sm + i * KSTR + d4) = *(const float4*)(src + DH);
        }
        __syncthreads();
        float s[4][4];
        #pragma unroll
        for (int i = 0; i < 4; i++)
            #pragma unroll
            for (int j = 0; j < 4; j++) s[i][j] = 0.f;
        for (int d4 = 0; d4 < DH; d4 += 4) {
            float4 qv[4], kv[4];
            #pragma unroll
            for (int i = 0; i < 4; i++) qv[i] = *(const float4*)(q_sm + (ty * 4 + i) * KSTR + d4);
            #pragma unroll
            for (int j = 0; j < 4; j++) kv[j] = *(const float4*)(k_sm + (tx * 4 + j) * KSTR + d4);
            #pragma unroll
            for (int i = 0; i < 4; i++)
                #pragma unroll
                for (int j = 0; j < 4; j++)
                    s[i][j] += qv[i].x * kv[j].x + qv[i].y * kv[j].y +
                               qv[i].z * kv[j].z + qv[i].w * kv[j].w;
        }
        float alpha[4];
        #pragma unroll
        for (int i = 0; i < 4; i++) {
            int qi = ty * 4 + i;
            float mx = -INFINITY;
            #pragma unroll
            for (int j = 0; j < 4; j++) {
                s[i][j] *= scale;
                if (jt == qt && (tx * 4 + j) > qi) s[i][j] = -INFINITY;
                mx = fmaxf(mx, s[i][j]);
            }
            #pragma unroll
            for (int msk = 8; msk; msk >>= 1)
                mx = fmaxf(mx, __shfl_xor_sync(0xffffffffu, mx, msk));
            float mnew = fmaxf(m_i[i], mx);
            float su = 0.f;
            #pragma unroll
            for (int j = 0; j < 4; j++) {
                float p = expf(s[i][j] - mnew);
                p_sm[qi * PSTR + tx * 4 + j] = p;
                su += p;
            }
            #pragma unroll
            for (int msk = 8; msk; msk >>= 1)
                su += __shfl_xor_sync(0xffffffffu, su, msk);
            alpha[i] = expf(m_i[i] - mnew);
            l_i[i] = l_i[i] * alpha[i] + su;
            m_i[i] = mnew;
        }
        __syncthreads();
        #pragma unroll
        for (int i = 0; i < 4; i++)
            #pragma unroll
            for (int j = 0; j < 8; j++) accO[i][j] *= alpha[i];
        for (int j = 0; j < KT; j++) {
            float4 v0 = *(const float4*)(v_sm + j * KSTR + tx * 8);
            float4 v1 = *(const float4*)(v_sm + j * KSTR + tx * 8 + 4);
            #pragma unroll
            for (int i = 0; i < 4; i++) {
                float p = p_sm[(ty * 4 + i) * PSTR + j];
                accO[i][0] += p * v0.x; accO[i][1] += p * v0.y;
                accO[i][2] += p * v0.z; accO[i][3] += p * v0.w;
                accO[i][4] += p * v1.x; accO[i][5] += p * v1.y;
                accO[i][6] += p * v1.z; accO[i][7] += p * v1.w;
            }
        }
    }
    #pragma unroll
    for (int i = 0; i < 4; i++) {
        float inv = 1.0f / l_i[i];
        float* op = g_attn + (rowbase + ty * 4 + i) * AINNER + h * DH + tx * 8;
        *(float4*)(op)     = make_float4(accO[i][0] * inv, accO[i][1] * inv,
                                         accO[i][2] * inv, accO[i][3] * inv);
        *(float4*)(op + 4) = make_float4(accO[i][4] * inv, accO[i][5] * inv,
                                         accO[i][6] * inv, accO[i][7] * inv);
    }
}

// ======================= SwiGLU -> bf16 split (compact [NROWS, FFI]) =======================
__global__ void swiglu_split_kernel() {
    int idx = blockIdx.x * 256 + threadIdx.x;
    int r  = idx >> 11;
    int c4 = (idx & 2047) << 2;
    const float* base = g_proj + (size_t)r * FUSEDW + (AINNER + 2 * DH);
    float4 xv = *(const float4*)(base + c4);
    float4 gv = *(const float4*)(base + FFI + c4);
    float o0 = xv.x * (gv.x / (1.f + expf(-gv.x)));
    float o1 = xv.y * (gv.y / (1.f + expf(-gv.y)));
    float o2 = xv.z * (gv.z / (1.f + expf(-gv.z)));
    float o3 = xv.w * (gv.w / (1.f + expf(-gv.w)));
    size_t o = (size_t)r * FFI + c4;
    split2(o0, g_ff_h, g_ff_l, o + 0);
    split2(o1, g_ff_h, g_ff_l, o + 1);
    split2(o2, g_ff_h, g_ff_l, o + 2);
    split2(o3, g_ff_h, g_ff_l, o + 3);
}

// ======================= launch =======================
extern "C" void kernel_launch(void* const* d_in, const int* in_sizes, int n_in,
                              void* d_out, int out_size) {
    const float* x          = (const float*)d_in[0];
    const float* gamma      = (const float*)d_in[1];
    const float* beta       = (const float*)d_in[2];
    const float* w_fused    = (const float*)d_in[3];
    const float* w_attn_out = (const float*)d_in[4];
    const float* w_ff_out   = (const float*)d_in[5];
    float* out = (float*)d_out;

    void *p;
    float *gp, *ga;
    __nv_bfloat16 *hh, *hl, *wfh, *wfl, *wah, *wal, *woh, *wol, *ath, *atl, *ffh, *ffl;
    cudaGetSymbolAddress(&p, g_proj); gp  = (float*)p;
    cudaGetSymbolAddress(&p, g_attn); ga  = (float*)p;
    cudaGetSymbolAddress(&p, g_h_hi); hh  = (__nv_bfloat16*)p;
    cudaGetSymbolAddress(&p, g_h_lo); hl  = (__nv_bfloat16*)p;
    cudaGetSymbolAddress(&p, g_wf_h); wfh = (__nv_bfloat16*)p;
    cudaGetSymbolAddress(&p, g_wf_l); wfl = (__nv_bfloat16*)p;
    cudaGetSymbolAddress(&p, g_wa_h); wah = (__nv_bfloat16*)p;
    cudaGetSymbolAddress(&p, g_wa_l); wal = (__nv_bfloat16*)p;
    cudaGetSymbolAddress(&p, g_wo_h); woh = (__nv_bfloat16*)p;
    cudaGetSymbolAddress(&p, g_wo_l); wol = (__nv_bfloat16*)p;
    cudaGetSymbolAddress(&p, g_at_h); ath = (__nv_bfloat16*)p;
    cudaGetSymbolAddress(&p, g_at_l); atl = (__nv_bfloat16*)p;
    cudaGetSymbolAddress(&p, g_ff_h); ffh = (__nv_bfloat16*)p;
    cudaGetSymbolAddress(&p, g_ff_l); ffl = (__nv_bfloat16*)p;

    cudaFuncSetAttribute(gemm_tc, cudaFuncAttributeMaxDynamicSharedMemorySize, GEMM_SMEM);
    cudaFuncSetAttribute(attn_kernel, cudaFuncAttributeMaxDynamicSharedMemorySize, FA_SMEM);

    // weight transpose + split (K-major [N,K] bf16 hi/lo)
    transpose_split<<<dim3(FUSEDW / 32, DIMX / 32), dim3(32, 8)>>>(w_fused, DIMX, FUSEDW, wfh, wfl);
    transpose_split<<<dim3(DIMX / 32, AINNER / 32), dim3(32, 8)>>>(w_attn_out, AINNER, DIMX, wah, wal);
    transpose_split<<<dim3(DIMX / 32, FFI / 32), dim3(32, 8)>>>(w_ff_out, FFI, DIMX, woh, wol);

    ln_split_kernel<<<NROWS, 256>>>(x, gamma, beta);

    // fused projection: g_proj = h @ w_fused
    gemm_tc<<<dim3(NROWS / 128, FUSEDW / 128), 256, GEMM_SMEM>>>(
        hh, hl, wfh, wfl, DIMX,
        nullptr, nullptr, nullptr, nullptr, 0,
        gp, FUSEDW);

    rope_kernel<<<NROWS, 256>>>();
    attn_kernel<<<dim3(SEQ / QT, 2 * HEADS), 256, FA_SMEM>>>();

    split_flat<<<(NROWS * (AINNER / 4)) / 256, 256>>>(ga, ath, atl);
    swiglu_split_kernel<<<(NROWS * (FFI / 4)) / 256, 256>>>();

    // out = attn_out @ w_attn_out + ff @ w_ff_out (accumulated in registers)
    gemm_tc<<<dim3(NROWS / 128, DIMX / 128), 256, GEMM_SMEM>>>(
        ath, atl, wah, wal, AINNER,
        ffh, ffl, woh, wol, FFI,
        out, DIMX);
}

// round 4
// speedup vs baseline: 2.1155x; 1.2511x over previous
#include <cuda_runtime.h>
#include <cuda_bf16.h>
#include <math.h>
#include <stdint.h>

#define DIMX    2048
#define HEADS   16
#define DH      128
#define AINNER  2048      // HEADS*DH
#define FFI     8192
#define FUSEDW  18688     // AINNER + 2*DH + 2*FFI
#define SEQ     2048
#define NROWS   4096      // B*N

// ======================= scratch (static device) =======================
static __device__ float g_proj[(size_t)NROWS * FUSEDW];  // 306 MB
static __device__ __nv_bfloat16 g_h_hi[(size_t)NROWS * DIMX],   g_h_lo[(size_t)NROWS * DIMX];
static __device__ __nv_bfloat16 g_wf_h[(size_t)FUSEDW * DIMX],  g_wf_l[(size_t)FUSEDW * DIMX];
static __device__ __nv_bfloat16 g_wa_h[(size_t)DIMX * AINNER],  g_wa_l[(size_t)DIMX * AINNER];
static __device__ __nv_bfloat16 g_wo_h[(size_t)DIMX * FFI],     g_wo_l[(size_t)DIMX * FFI];
static __device__ __nv_bfloat16 g_at_h[(size_t)NROWS * AINNER], g_at_l[(size_t)NROWS * AINNER];
static __device__ __nv_bfloat16 g_ff_h[(size_t)NROWS * FFI],    g_ff_l[(size_t)NROWS * FFI];
// attention operands: q per (b,h), k/v per b (MQA)
static __device__ __nv_bfloat16 g_q_h[(size_t)2 * HEADS * SEQ * DH], g_q_l[(size_t)2 * HEADS * SEQ * DH];
static __device__ __nv_bfloat16 g_k_h[(size_t)2 * SEQ * DH],         g_k_l[(size_t)2 * SEQ * DH];
static __device__ __nv_bfloat16 g_v_h[(size_t)2 * SEQ * DH],         g_v_l[(size_t)2 * SEQ * DH];

__device__ __forceinline__ void split2(float v, __nv_bfloat16* H, __nv_bfloat16* L, size_t o) {
    __nv_bfloat16 h = __float2bfloat16(v);
    H[o] = h;
    L[o] = __float2bfloat16(v - __bfloat162float(h));
}

__device__ __forceinline__ uint32_t smem_u32(const void* p) {
    uint32_t a;
    asm("{ .reg .u64 t; cvta.to.shared.u64 t, %1; cvt.u32.u64 %0, t; }" : "=r"(a) : "l"(p));
    return a;
}
__device__ __forceinline__ void ldmx4(uint32_t* r, uint32_t addr) {
    asm volatile("ldmatrix.sync.aligned.m8n8.x4.shared.b16 {%0,%1,%2,%3}, [%4];"
                 : "=r"(r[0]), "=r"(r[1]), "=r"(r[2]), "=r"(r[3]) : "r"(addr));
}
__device__ __forceinline__ void ldmx4t(uint32_t* r, uint32_t addr) {
    asm volatile("ldmatrix.sync.aligned.m8n8.x4.trans.shared.b16 {%0,%1,%2,%3}, [%4];"
                 : "=r"(r[0]), "=r"(r[1]), "=r"(r[2]), "=r"(r[3]) : "r"(addr));
}
__device__ __forceinline__ void mma_bf16(float* c, const uint32_t* a, uint32_t b0, uint32_t b1) {
    asm volatile(
        "mma.sync.aligned.m16n8k16.row.col.f32.bf16.bf16.f32 "
        "{%0,%1,%2,%3}, {%4,%5,%6,%7}, {%8,%9}, {%0,%1,%2,%3};"
        : "+f"(c[0]), "+f"(c[1]), "+f"(c[2]), "+f"(c[3])
        : "r"(a[0]), "r"(a[1]), "r"(a[2]), "r"(a[3]), "r"(b0), "r"(b1));
}
__device__ __forceinline__ uint32_t pack_bf16x2(float lo, float hi) {
    uint32_t r;
    asm("cvt.rn.bf16x2.f32 %0, %1, %2;" : "=r"(r) : "f"(hi), "f"(lo));
    return r;
}
#define CP_ASYNC16(sa, ga) \
    asm volatile("cp.async.cg.shared.global [%0], [%1], 16;" :: "r"(sa), "l"(ga))
#define CP_COMMIT()  asm volatile("cp.async.commit_group;" ::: "memory")
#define CP_WAIT0()   asm volatile("cp.async.wait_group 0;" ::: "memory")
#define CP_WAIT1()   asm volatile("cp.async.wait_group 1;" ::: "memory")
#define CP_WAIT2()   asm volatile("cp.async.wait_group 2;" ::: "memory")

// ======================= LayerNorm -> bf16 split =======================
__global__ void ln_split_kernel(const float* __restrict__ x,
                                const float* __restrict__ gamma,
                                const float* __restrict__ beta) {
    int r = blockIdx.x;
    const float* xr = x + (size_t)r * DIMX;
    float s = 0.f, s2 = 0.f;
    for (int i = threadIdx.x; i < DIMX; i += 256) {
        float v = xr[i]; s += v; s2 += v * v;
    }
    #pragma unroll
    for (int m = 16; m; m >>= 1) {
        s  += __shfl_xor_sync(0xffffffffu, s,  m);
        s2 += __shfl_xor_sync(0xffffffffu, s2, m);
    }
    __shared__ float red0[8], red1[8];
    int w = threadIdx.x >> 5, l = threadIdx.x & 31;
    if (l == 0) { red0[w] = s; red1[w] = s2; }
    __syncthreads();
    __shared__ float smu, srstd;
    if (threadIdx.x == 0) {
        float a = 0.f, b2 = 0.f;
        #pragma unroll
        for (int i = 0; i < 8; i++) { a += red0[i]; b2 += red1[i]; }
        float mu  = a / DIMX;
        float var = b2 / DIMX - mu * mu;
        smu = mu; srstd = 1.0f / sqrtf(var + 1e-5f);
    }
    __syncthreads();
    float mu = smu, rstd = srstd;
    for (int i = threadIdx.x; i < DIMX; i += 256) {
        float v = (xr[i] - mu) * rstd * gamma[i] + beta[i];
        split2(v, g_h_hi, g_h_lo, (size_t)r * DIMX + i);
    }
}

// ======================= transpose + split: W[K,N] -> T[N,K] bf16 hi/lo =======================
__global__ void transpose_split(const float* __restrict__ W, int K, int N,
                                __nv_bfloat16* __restrict__ Th, __nv_bfloat16* __restrict__ Tl) {
    __shared__ float t[32][33];
    int n0 = blockIdx.x * 32, k0 = blockIdx.y * 32;
    int tx = threadIdx.x, ty = threadIdx.y;
    for (int j = ty; j < 32; j += 8)
        t[j][tx] = W[(size_t)(k0 + j) * N + n0 + tx];
    __syncthreads();
    for (int j = ty; j < 32; j += 8) {
        float v = t[tx][j];
        split2(v, Th, Tl, (size_t)(n0 + j) * K + k0 + tx);
    }
}

// ======================= mma.sync dual-phase GEMM (3-stage cp.async) =======================
#define BKC 32
#define ASTRIDE 80
#define MAT_BYTES (128 * ASTRIDE)      // 10240
#define STAGE_BYTES (4 * MAT_BYTES)    // 40960 (Ah, Al, Bh, Bl)
#define GEMM_SMEM (3 * STAGE_BYTES)    // 122880

__global__ __launch_bounds__(256, 1)
void gemm_tc(const __nv_bfloat16* __restrict__ Ah1, const __nv_bfloat16* __restrict__ Al1,
             const __nv_bfloat16* __restrict__ Bh1, const __nv_bfloat16* __restrict__ Bl1, int K1,
             const __nv_bfloat16* __restrict__ Ah2, const __nv_bfloat16* __restrict__ Al2,
             const __nv_bfloat16* __restrict__ Bh2, const __nv_bfloat16* __restrict__ Bl2, int K2,
             float* __restrict__ C, int ldc) {
    extern __shared__ char smem[];
    uint32_t smb = smem_u32(smem);
    int tid = threadIdx.x;
    int w = tid >> 5, l = tid & 31;
    int wm = w & 3, wn = w >> 2;
    int m0 = blockIdx.x * 128;
    int n0 = blockIdx.y * 128;
    int S1 = K1 / BKC, S2 = K2 / BKC, S = S1 + S2;

    float acc[2][8][4];
    #pragma unroll
    for (int t = 0; t < 2; t++)
        #pragma unroll
        for (int n = 0; n < 8; n++)
            #pragma unroll
            for (int j = 0; j < 4; j++) acc[t][n][j] = 0.f;

    auto issue = [&](int s) {
        const __nv_bfloat16 *ah, *al, *bh, *bl; int K, k0;
        if (s < S1) { ah = Ah1; al = Al1; bh = Bh1; bl = Bl1; K = K1; k0 = s * BKC; }
        else        { ah = Ah2; al = Al2; bh = Bh2; bl = Bl2; K = K2; k0 = (s - S1) * BKC; }
        uint32_t sb0 = smb + (s % 3) * STAGE_BYTES;
        #pragma unroll
        for (int t = 0; t < 8; t++) {
            int q = tid + (t << 8);
            int mat = q >> 9;
            int rem = q & 511;
            int row = rem >> 2;
            int c   = rem & 3;
            const __nv_bfloat16* g = (mat == 0) ? ah : (mat == 1) ? al : (mat == 2) ? bh : bl;
            int rb = (mat < 2) ? m0 : n0;
            const __nv_bfloat16* gp = g + (size_t)(rb + row) * K + k0 + c * 8;
            uint32_t sa = sb0 + mat * MAT_BYTES + row * ASTRIDE + c * 16;
            CP_ASYNC16(sa, gp);
        }
        CP_COMMIT();
    };

    issue(0);
    if (S > 1) issue(1);
    for (int s = 0; s < S; ++s) {
        if (s + 2 < S) issue(s + 2);
        else CP_COMMIT();
        CP_WAIT2();
        __syncthreads();

        uint32_t sA = smb + (s % 3) * STAGE_BYTES;
        uint32_t sB = sA + 2 * MAT_BYTES;
        #pragma unroll
        for (int kk = 0; kk < BKC; kk += 16) {
            uint32_t ahf[2][4], alf[2][4];
            #pragma unroll
            for (int t = 0; t < 2; t++) {
                uint32_t ro = (uint32_t)((wm * 32 + t * 16 + ((l >> 3) & 1) * 8 + (l & 7)) * ASTRIDE
                                         + ((kk >> 3) + (l >> 4)) * 16);
                ldmx4(ahf[t], sA + ro);
                ldmx4(alf[t], sA + MAT_BYTES + ro);
            }
            #pragma unroll
            for (int u = 0; u < 4; u++) {
                uint32_t bo = (uint32_t)((wn * 64 + u * 16 + (l >> 4) * 8 + (l & 7)) * ASTRIDE
                                         + ((kk >> 3) + ((l >> 3) & 1)) * 16);
                uint32_t bhf[4], blf[4];
                ldmx4(bhf, sB + bo);
                ldmx4(blf, sB + MAT_BYTES + bo);
                #pragma unroll
                for (int t = 0; t < 2; t++) {
                    #pragma unroll
                    for (int h = 0; h < 2; h++) {
                        float* c = acc[t][u * 2 + h];
                        mma_bf16(c, ahf[t], bhf[h * 2], bhf[h * 2 + 1]);
                        mma_bf16(c, ahf[t], blf[h * 2], blf[h * 2 + 1]);
                        mma_bf16(c, alf[t], bhf[h * 2], bhf[h * 2 + 1]);
                    }
                }
            }
        }
        __syncthreads();
    }

    #pragma unroll
    for (int t = 0; t < 2; t++) {
        int row = m0 + wm * 32 + t * 16 + (l >> 2);
        #pragma unroll
        for (int n = 0; n < 8; n++) {
            int col = n0 + wn * 64 + n * 8 + (l & 3) * 2;
            *(float2*)(C + (size_t)row * ldc + col)       = make_float2(acc[t][n][0], acc[t][n][1]);
            *(float2*)(C + (size_t)(row + 8) * ldc + col) = make_float2(acc[t][n][2], acc[t][n][3]);
        }
    }
}

// ======================= rope + convert to bf16 attention operands =======================
__global__ void rope_convert_kernel() {
    int r = blockIdx.x;
    int b = r >> 11;                 // SEQ = 2048
    int n = r & (SEQ - 1);
    const float* row = g_proj + (size_t)r * FUSEDW;
    for (int idx = threadIdx.x; idx < 1152; idx += 256) {
        if (idx < 1024) {            // q: 16 heads x 64 pairs
            int head = idx >> 6, d = idx & 63;
            double invf = pow(10000.0, -(double)d / 64.0);
            float theta = (float)((double)n * invf);
            float c = (float)cos((double)theta);
            float s = (float)sin((double)theta);
            float t0 = row[head * DH + d], t1 = row[head * DH + d + 64];
            size_t base = ((size_t)(b * HEADS + head) * SEQ + n) * DH;
            split2(t0 * c - t1 * s, g_q_h, g_q_l, base + d);
            split2(t1 * c + t0 * s, g_q_h, g_q_l, base + d + 64);
        } else if (idx < 1088) {     // k: 64 pairs
            int d = idx - 1024;
            double invf = pow(10000.0, -(double)d / 64.0);
            float theta = (float)((double)n * invf);
            float c = (float)cos((double)theta);
            float s = (float)sin((double)theta);
            float t0 = row[AINNER + d], t1 = row[AINNER + d + 64];
            size_t base = ((size_t)b * SEQ + n) * DH;
            split2(t0 * c - t1 * s, g_k_h, g_k_l, base + d);
            split2(t1 * c + t0 * s, g_k_h, g_k_l, base + d + 64);
        } else {                     // v: 64 pairs, no rope
            int d = idx - 1088;
            float t0 = row[AINNER + DH + d], t1 = row[AINNER + DH + d + 64];
            size_t base = ((size_t)b * SEQ + n) * DH;
            split2(t0, g_v_h, g_v_l, base + d);
            split2(t1, g_v_h, g_v_l, base + d + 64);
        }
    }
}

// ======================= tensor-core flash attention (MQA, causal) =======================
// 64-query tile, 4 warps (16 q rows each), 64-key tiles double-buffered.
#define DSTR 272                        // 128 bf16 = 256B + 16B pad per row
#define ATB  (64 * DSTR)                // 17408 per matrix tile
#define AT_STG (4 * ATB)                // kh, kl, vh, vl per stage
#define ATTN_SMEM (2 * ATB + 2 * AT_STG)  // Q(hi,lo) + 2 stages = 174080

__global__ __launch_bounds__(128, 1)
void attn_mma_kernel() {
    extern __shared__ char asm_sm[];
    uint32_t smb = smem_u32(asm_sm);
    int tid = threadIdx.x, w = tid >> 5, l = tid & 31;
    int qt = gridDim.x - 1 - blockIdx.x;    // long blocks first
    int bh = blockIdx.y;
    int b = bh >> 4, h = bh & 15;

    const __nv_bfloat16* QH = g_q_h + ((size_t)bh * SEQ + qt * 64) * DH;
    const __nv_bfloat16* QL = g_q_l + ((size_t)bh * SEQ + qt * 64) * DH;
    const __nv_bfloat16* KH = g_k_h + (size_t)b * SEQ * DH;
    const __nv_bfloat16* KL = g_k_l + (size_t)b * SEQ * DH;
    const __nv_bfloat16* VH = g_v_h + (size_t)b * SEQ * DH;
    const __nv_bfloat16* VL = g_v_l + (size_t)b * SEQ * DH;

    auto issue_kv = [&](int jt) {
        uint32_t sb0 = smb + 2 * ATB + (jt & 1) * AT_STG;
        int rowg = jt * 64;
        #pragma unroll
        for (int t = 0; t < 32; t++) {
            int c = tid + (t << 7);          // 0..4095
            int mat = c >> 10;               // 0 kh, 1 kl, 2 vh, 3 vl
            int rem = c & 1023;
            int row = rem >> 4, ch = rem & 15;
            const __nv_bfloat16* g = (mat == 0) ? KH : (mat == 1) ? KL : (mat == 2) ? VH : VL;
            CP_ASYNC16(sb0 + mat * ATB + row * DSTR + ch * 16,
                       g + (size_t)(rowg + row) * DH + ch * 8);
        }
    };

    // Q load + first KV stage in group 0
    #pragma unroll
    for (int t = 0; t < 16; t++) {
        int c = tid + (t << 7);              // 0..2047
        int mat = c >> 10;
        int rem = c & 1023;
        int row = rem >> 4, ch = rem & 15;
        const __nv_bfloat16* g = mat ? QL : QH;
        CP_ASYNC16(smb + mat * ATB + row * DSTR + ch * 16, g + (size_t)row * DH + ch * 8);
    }
    issue_kv(0);
    CP_COMMIT();

    float acc_o[16][4];
    #pragma unroll
    for (int t = 0; t < 16; t++)
        #pragma unroll
        for (int j = 0; j < 4; j++) acc_o[t][j] = 0.f;
    float m_lo = -1e30f, m_hi = -1e30f, l_lo = 0.f, l_hi = 0.f;
    const float scale = 0.08838834764831845f;

    for (int jt = 0; jt <= qt; ++jt) {
        if (jt < qt) { issue_kv(jt + 1); CP_COMMIT(); CP_WAIT1(); }
        else CP_WAIT0();
        __syncthreads();

        uint32_t kh = smb + 2 * ATB + (jt & 1) * AT_STG;
        uint32_t kl = kh + ATB, vh = kh + 2 * ATB, vl = kh + 3 * ATB;

        // ---- S = Q K^T (3-term emulation) ----
        float s[8][4];
        #pragma unroll
        for (int j = 0; j < 8; j++)
            #pragma unroll
            for (int c = 0; c < 4; c++) s[j][c] = 0.f;
        #pragma unroll
        for (int kk = 0; kk < 8; kk++) {
            uint32_t qa = smb + (uint32_t)((w * 16 + (l & 15)) * DSTR + kk * 32 + (l >> 4) * 16);
            uint32_t aH[4], aL[4];
            ldmx4(aH, qa);
            ldmx4(aL, qa + ATB);
            #pragma unroll
            for (int j16 = 0; j16 < 4; j16++) {
                uint32_t ba = (uint32_t)((j16 * 16 + (l & 7) + ((l >= 16) ? 8 : 0)) * DSTR
                                         + kk * 32 + ((l >> 3) & 1) * 16);
                uint32_t bH[4], bL[4];
                ldmx4(bH, kh + ba);
                ldmx4(bL, kl + ba);
                float* s0 = s[2 * j16];
                float* s1 = s[2 * j16 + 1];
                mma_bf16(s0, aH, bH[0], bH[1]);
                mma_bf16(s0, aH, bL[0], bL[1]);
                mma_bf16(s0, aL, bH[0], bH[1]);
                mma_bf16(s1, aH, bH[2], bH[3]);
                mma_bf16(s1, aH, bL[2], bL[3]);
                mma_bf16(s1, aL, bH[2], bH[3]);
            }
        }

        // ---- softmax (warp-local; each lane owns rows r_lo=l>>2, r_hi=r_lo+8) ----
        int r_lo = l >> 2;
        int qrow_lo = w * 16 + r_lo, qrow_hi = qrow_lo + 8;
        float mx0 = -1e30f, mx1 = -1e30f;
        #pragma unroll
        for (int j = 0; j < 8; j++) {
            int col = j * 8 + (l & 3) * 2;
            #pragma unroll
            for (int c = 0; c < 4; c++) s[j][c] *= scale;
            if (jt == qt) {
                if (col     > qrow_lo) s[j][0] = -1e30f;
                if (col + 1 > qrow_lo) s[j][1] = -1e30f;
                if (col     > qrow_hi) s[j][2] = -1e30f;
                if (col + 1 > qrow_hi) s[j][3] = -1e30f;
            }
            mx0 = fmaxf(mx0, fmaxf(s[j][0], s[j][1]));
            mx1 = fmaxf(mx1, fmaxf(s[j][2], s[j][3]));
        }
        mx0 = fmaxf(mx0, __shfl_xor_sync(0xffffffffu, mx0, 1));
        mx0 = fmaxf(mx0, __shfl_xor_sync(0xffffffffu, mx0, 2));
        mx1 = fmaxf(mx1, __shfl_xor_sync(0xffffffffu, mx1, 1));
        mx1 = fmaxf(mx1, __shfl_xor_sync(0xffffffffu, mx1, 2));
        float mn0 = fmaxf(m_lo, mx0), mn1 = fmaxf(m_hi, mx1);
        float al0 = __expf(m_lo - mn0), al1 = __expf(m_hi - mn1);
        float su0 = 0.f, su1 = 0.f;
        #pragma unroll
        for (int j = 0; j < 8; j++) {
            s[j][0] = __expf(s[j][0] - mn0);
            s[j][1] = __expf(s[j][1] - mn0);
            s[j][2] = __expf(s[j][2] - mn1);
            s[j][3] = __expf(s[j][3] - mn1);
            su0 += s[j][0] + s[j][1];
            su1 += s[j][2] + s[j][3];
        }
        su0 += __shfl_xor_sync(0xffffffffu, su0, 1);
        su0 += __shfl_xor_sync(0xffffffffu, su0, 2);
        su1 += __shfl_xor_sync(0xffffffffu, su1, 1);
        su1 += __shfl_xor_sync(0xffffffffu, su1, 2);
        l_lo = l_lo * al0 + su0;
        l_hi = l_hi * al1 + su1;
        m_lo = mn0; m_hi = mn1;
        #pragma unroll
        for (int t = 0; t < 16; t++) {
            acc_o[t][0] *= al0; acc_o[t][1] *= al0;
            acc_o[t][2] *= al1; acc_o[t][3] *= al1;
        }

        // ---- O += P V (P split hi/lo in registers; 3-term) ----
        #pragma unroll
        for (int j16 = 0; j16 < 4; j16++) {
            float* t0 = s[2 * j16];
            float* t1 = s[2 * j16 + 1];
            uint32_t ph[4], pl[4];
            #pragma unroll
            for (int q = 0; q < 4; q++) {
                const float* tt = (q < 2) ? t0 : t1;
                float p0 = tt[(q & 1) * 2], p1 = tt[(q & 1) * 2 + 1];
                float h0 = __bfloat162float(__float2bfloat16(p0));
                float h1 = __bfloat162float(__float2bfloat16(p1));
                ph[q] = pack_bf16x2(h0, h1);
                pl[q] = pack_bf16x2(p0 - h0, p1 - h1);
            }
            #pragma unroll
            for (int d16 = 0; d16 < 8; d16++) {
                uint32_t va = (uint32_t)((j16 * 16 + (l & 7) + ((l >> 3) & 1) * 8) * DSTR
                                         + d16 * 32 + ((l >= 16) ? 16 : 0));
                uint32_t bH[4], bL[4];
                ldmx4t(bH, vh + va);
                ldmx4t(bL, vl + va);
                float* o0 = acc_o[2 * d16];
                float* o1 = acc_o[2 * d16 + 1];
                mma_bf16(o0, ph, bH[0], bH[1]);
                mma_bf16(o0, ph, bL[0], bL[1]);
                mma_bf16(o0, pl, bH[0], bH[1]);
                mma_bf16(o1, ph, bH[2], bH[3]);
                mma_bf16(o1, ph, bL[2], bL[3]);
                mma_bf16(o1, pl, bH[2], bH[3]);
            }
        }
        __syncthreads();
    }

    // ---- epilogue: normalize and write bf16 hi/lo into g_at ----
    float inv0 = 1.0f / l_lo, inv1 = 1.0f / l_hi;
    size_t row0 = (size_t)(b * SEQ + qt * 64 + w * 16 + (l >> 2));
    #pragma unroll
    for (int t = 0; t < 16; t++) {
        int col = h * DH + t * 8 + (l & 3) * 2;
        float v0 = acc_o[t][0] * inv0, v1 = acc_o[t][1] * inv0;
        float v2 = acc_o[t][2] * inv1, v3 = acc_o[t][3] * inv1;
        split2(v0, g_at_h, g_at_l, row0 * AINNER + col);
        split2(v1, g_at_h, g_at_l, row0 * AINNER + col + 1);
        split2(v2, g_at_h, g_at_l, (row0 + 8) * AINNER + col);
        split2(v3, g_at_h, g_at_l, (row0 + 8) * AINNER + col + 1);
    }
}

// ======================= SwiGLU -> bf16 split (compact [NROWS, FFI]) =======================
__global__ void swiglu_split_kernel() {
    int idx = blockIdx.x * 256 + threadIdx.x;
    int r  = idx >> 11;
    int c4 = (idx & 2047) << 2;
    const float* base = g_proj + (size_t)r * FUSEDW + (AINNER + 2 * DH);
    float4 xv = *(const float4*)(base + c4);
    float4 gv = *(const float4*)(base + FFI + c4);
    float o0 = xv.x * (gv.x / (1.f + __expf(-gv.x)));
    float o1 = xv.y * (gv.y / (1.f + __expf(-gv.y)));
    float o2 = xv.z * (gv.z / (1.f + __expf(-gv.z)));
    float o3 = xv.w * (gv.w / (1.f + __expf(-gv.w)));
    size_t o = (size_t)r * FFI + c4;
    split2(o0, g_ff_h, g_ff_l, o + 0);
    split2(o1, g_ff_h, g_ff_l, o + 1);
    split2(o2, g_ff_h, g_ff_l, o + 2);
    split2(o3, g_ff_h, g_ff_l, o + 3);
}

// ======================= launch =======================
extern "C" void kernel_launch(void* const* d_in, const int* in_sizes, int n_in,
                              void* d_out, int out_size) {
    const float* x          = (const float*)d_in[0];
    const float* gamma      = (const float*)d_in[1];
    const float* beta       = (const float*)d_in[2];
    const float* w_fused    = (const float*)d_in[3];
    const float* w_attn_out = (const float*)d_in[4];
    const float* w_ff_out   = (const float*)d_in[5];
    float* out = (float*)d_out;

    void *p;
    float *gp;
    __nv_bfloat16 *hh, *hl, *wfh, *wfl, *wah, *wal, *woh, *wol, *ath, *atl, *ffh, *ffl;
    cudaGetSymbolAddress(&p, g_proj); gp  = (float*)p;
    cudaGetSymbolAddress(&p, g_h_hi); hh  = (__nv_bfloat16*)p;
    cudaGetSymbolAddress(&p, g_h_lo); hl  = (__nv_bfloat16*)p;
    cudaGetSymbolAddress(&p, g_wf_h); wfh = (__nv_bfloat16*)p;
    cudaGetSymbolAddress(&p, g_wf_l); wfl = (__nv_bfloat16*)p;
    cudaGetSymbolAddress(&p, g_wa_h); wah = (__nv_bfloat16*)p;
    cudaGetSymbolAddress(&p, g_wa_l); wal = (__nv_bfloat16*)p;
    cudaGetSymbolAddress(&p, g_wo_h); woh = (__nv_bfloat16*)p;
    cudaGetSymbolAddress(&p, g_wo_l); wol = (__nv_bfloat16*)p;
    cudaGetSymbolAddress(&p, g_at_h); ath = (__nv_bfloat16*)p;
    cudaGetSymbolAddress(&p, g_at_l); atl = (__nv_bfloat16*)p;
    cudaGetSymbolAddress(&p, g_ff_h); ffh = (__nv_bfloat16*)p;
    cudaGetSymbolAddress(&p, g_ff_l); ffl = (__nv_bfloat16*)p;

    cudaFuncSetAttribute(gemm_tc, cudaFuncAttributeMaxDynamicSharedMemorySize, GEMM_SMEM);
    cudaFuncSetAttribute(attn_mma_kernel, cudaFuncAttributeMaxDynamicSharedMemorySize, ATTN_SMEM);

    // weight transpose + split (K-major [N,K] bf16 hi/lo)
    transpose_split<<<dim3(FUSEDW / 32, DIMX / 32), dim3(32, 8)>>>(w_fused, DIMX, FUSEDW, wfh, wfl);
    transpose_split<<<dim3(DIMX / 32, AINNER / 32), dim3(32, 8)>>>(w_attn_out, AINNER, DIMX, wah, wal);
    transpose_split<<<dim3(DIMX / 32, FFI / 32), dim3(32, 8)>>>(w_ff_out, FFI, DIMX, woh, wol);

    ln_split_kernel<<<NROWS, 256>>>(x, gamma, beta);

    // fused projection: g_proj = h @ w_fused
    gemm_tc<<<dim3(NROWS / 128, FUSEDW / 128), 256, GEMM_SMEM>>>(
        hh, hl, wfh, wfl, DIMX,
        nullptr, nullptr, nullptr, nullptr, 0,
        gp, FUSEDW);

    rope_convert_kernel<<<NROWS, 256>>>();

    attn_mma_kernel<<<dim3(SEQ / 64, 2 * HEADS), 128, ATTN_SMEM>>>();

    swiglu_split_kernel<<<(NROWS * (FFI / 4)) / 256, 256>>>();

    // out = attn_out @ w_attn_out + ff @ w_ff_out (accumulated in registers)
    gemm_tc<<<dim3(NROWS / 128, DIMX / 128), 256, GEMM_SMEM>>>(
        ath, atl, wah, wal, AINNER,
        ffh, ffl, woh, wol, FFI,
        out, DIMX);
}

// round 5
// speedup vs baseline: 3.3001x; 1.5599x over previous
#include <cuda_runtime.h>
#include <cuda_bf16.h>
#include <math.h>
#include <stdint.h>

#define DIMX    2048
#define HEADS   16
#define DH      128
#define AINNER  2048      // HEADS*DH
#define FFI     8192
#define FUSEDW  18688     // AINNER + 2*DH + 2*FFI
#define QKVW    2304      // AINNER + 2*DH
#define SEQ     2048
#define NROWS   4096      // B*N

// ======================= scratch (static device) =======================
static __device__ float g_qkv[(size_t)NROWS * QKVW];     // 37.7 MB (fp32 q|k|v)
static __device__ float2 g_trig[SEQ * 64];
static __device__ __nv_bfloat16 g_h_hi[(size_t)NROWS * DIMX],   g_h_lo[(size_t)NROWS * DIMX];
static __device__ __nv_bfloat16 g_wf_h[(size_t)FUSEDW * DIMX],  g_wf_l[(size_t)FUSEDW * DIMX];
static __device__ __nv_bfloat16 g_wa_h[(size_t)DIMX * AINNER],  g_wa_l[(size_t)DIMX * AINNER];
static __device__ __nv_bfloat16 g_wo_h[(size_t)DIMX * FFI],     g_wo_l[(size_t)DIMX * FFI];
static __device__ __nv_bfloat16 g_at_h[(size_t)NROWS * AINNER], g_at_l[(size_t)NROWS * AINNER];
static __device__ __nv_bfloat16 g_ff_h[(size_t)NROWS * FFI],    g_ff_l[(size_t)NROWS * FFI];
static __device__ __nv_bfloat16 g_q_h[(size_t)2 * HEADS * SEQ * DH], g_q_l[(size_t)2 * HEADS * SEQ * DH];
static __device__ __nv_bfloat16 g_k_h[(size_t)2 * SEQ * DH],         g_k_l[(size_t)2 * SEQ * DH];
static __device__ __nv_bfloat16 g_v_h[(size_t)2 * SEQ * DH],         g_v_l[(size_t)2 * SEQ * DH];

__device__ __forceinline__ void split2(float v, __nv_bfloat16* H, __nv_bfloat16* L, size_t o) {
    __nv_bfloat16 h = __float2bfloat16(v);
    H[o] = h;
    L[o] = __float2bfloat16(v - __bfloat162float(h));
}
__device__ __forceinline__ uint32_t smem_u32(const void* p) {
    uint32_t a;
    asm("{ .reg .u64 t; cvta.to.shared.u64 t, %1; cvt.u32.u64 %0, t; }" : "=r"(a) : "l"(p));
    return a;
}
__device__ __forceinline__ void ldmx4(uint32_t* r, uint32_t addr) {
    asm volatile("ldmatrix.sync.aligned.m8n8.x4.shared.b16 {%0,%1,%2,%3}, [%4];"
                 : "=r"(r[0]), "=r"(r[1]), "=r"(r[2]), "=r"(r[3]) : "r"(addr));
}
__device__ __forceinline__ void ldmx4t(uint32_t* r, uint32_t addr) {
    asm volatile("ldmatrix.sync.aligned.m8n8.x4.trans.shared.b16 {%0,%1,%2,%3}, [%4];"
                 : "=r"(r[0]), "=r"(r[1]), "=r"(r[2]), "=r"(r[3]) : "r"(addr));
}
__device__ __forceinline__ void mma_bf16(float* c, const uint32_t* a, uint32_t b0, uint32_t b1) {
    asm volatile(
        "mma.sync.aligned.m16n8k16.row.col.f32.bf16.bf16.f32 "
        "{%0,%1,%2,%3}, {%4,%5,%6,%7}, {%8,%9}, {%0,%1,%2,%3};"
        : "+f"(c[0]), "+f"(c[1]), "+f"(c[2]), "+f"(c[3])
        : "r"(a[0]), "r"(a[1]), "r"(a[2]), "r"(a[3]), "r"(b0), "r"(b1));
}
__device__ __forceinline__ uint32_t pack_bf16x2(float lo, float hi) {
    uint32_t r;
    asm("cvt.rn.bf16x2.f32 %0, %1, %2;" : "=r"(r) : "f"(hi), "f"(lo));
    return r;
}
#define CP_ASYNC16(sa, ga) \
    asm volatile("cp.async.cg.shared.global [%0], [%1], 16;" :: "r"(sa), "l"(ga))
#define CP_COMMIT()  asm volatile("cp.async.commit_group;" ::: "memory")
#define CP_WAIT0()   asm volatile("cp.async.wait_group 0;" ::: "memory")
#define CP_WAIT1()   asm volatile("cp.async.wait_group 1;" ::: "memory")
#define CP_WAIT2()   asm volatile("cp.async.wait_group 2;" ::: "memory")

// ======================= trig table =======================
__global__ void trig_kernel() {
    int n = blockIdx.x, d = threadIdx.x;      // 2048 x 64
    double invf = pow(10000.0, -(double)d / 64.0);
    float theta = (float)((double)n * invf);
    g_trig[n * 64 + d] = make_float2((float)cos((double)theta), (float)sin((double)theta));
}

// ======================= LayerNorm -> bf16 split =======================
__global__ void ln_split_kernel(const float* __restrict__ x,
                                const float* __restrict__ gamma,
                                const float* __restrict__ beta) {
    int r = blockIdx.x;
    const float* xr = x + (size_t)r * DIMX;
    float s = 0.f, s2 = 0.f;
    for (int i = threadIdx.x; i < DIMX; i += 256) {
        float v = xr[i]; s += v; s2 += v * v;
    }
    #pragma unroll
    for (int m = 16; m; m >>= 1) {
        s  += __shfl_xor_sync(0xffffffffu, s,  m);
        s2 += __shfl_xor_sync(0xffffffffu, s2, m);
    }
    __shared__ float red0[8], red1[8];
    int w = threadIdx.x >> 5, l = threadIdx.x & 31;
    if (l == 0) { red0[w] = s; red1[w] = s2; }
    __syncthreads();
    __shared__ float smu, srstd;
    if (threadIdx.x == 0) {
        float a = 0.f, b2 = 0.f;
        #pragma unroll
        for (int i = 0; i < 8; i++) { a += red0[i]; b2 += red1[i]; }
        float mu  = a / DIMX;
        float var = b2 / DIMX - mu * mu;
        smu = mu; srstd = 1.0f / sqrtf(var + 1e-5f);
    }
    __syncthreads();
    float mu = smu, rstd = srstd;
    for (int i = threadIdx.x; i < DIMX; i += 256) {
        float v = (xr[i] - mu) * rstd * gamma[i] + beta[i];
        split2(v, g_h_hi, g_h_lo, (size_t)r * DIMX + i);
    }
}

// ======================= transpose + split (optional ff interleave remap) ==============
__global__ void transpose_split(const float* __restrict__ W, int K, int N, int remap,
                                __nv_bfloat16* __restrict__ Th, __nv_bfloat16* __restrict__ Tl) {
    __shared__ float t[32][33];
    int n0 = blockIdx.x * 32, k0 = blockIdx.y * 32;
    int tx = threadIdx.x, ty = threadIdx.y;
    for (int j = ty; j < 32; j += 8) {
        int oc = n0 + tx;                     // output (transposed) row index
        int sc = oc;
        if (remap && oc >= QKVW) {
            int lf = oc - QKVW;
            sc = QKVW + (lf >> 1) + ((lf & 1) ? FFI : 0);
        }
        t[j][tx] = W[(size_t)(k0 + j) * N + sc];
    }
    __syncthreads();
    for (int j = ty; j < 32; j += 8) {
        float v = t[tx][j];
        split2(v, Th, Tl, (size_t)(n0 + j) * K + k0 + tx);
    }
}

// ======================= mma.sync dual-phase GEMM (BK=64, swizzled, 3-stage) ==========
#define BKC 64
#define MATB (128 * 128)               // bytes per matrix tile (128 rows x 128B)
#define STAGE_BYTES (4 * MATB)         // 65536 (Ah, Al, Bh, Bl)
#define GEMM_SMEM (3 * STAGE_BYTES)    // 196608
#define SW8(row, ch) ((uint32_t)((row) * 128 + (((ch) ^ ((row) & 7)) << 4)))

__global__ __launch_bounds__(256, 1)
void gemm_tc(const __nv_bfloat16* __restrict__ Ah1, const __nv_bfloat16* __restrict__ Al1,
             const __nv_bfloat16* __restrict__ Bh1, const __nv_bfloat16* __restrict__ Bl1, int K1,
             const __nv_bfloat16* __restrict__ Ah2, const __nv_bfloat16* __restrict__ Al2,
             const __nv_bfloat16* __restrict__ Bh2, const __nv_bfloat16* __restrict__ Bl2, int K2,
             float* __restrict__ C, int ldc, int mode) {
    extern __shared__ char smem[];
    uint32_t smb = smem_u32(smem);
    int tid = threadIdx.x;
    int w = tid >> 5, l = tid & 31;
    int wm = w & 3, wn = w >> 2;
    int m0 = blockIdx.x * 128;
    int n0 = blockIdx.y * 128;
    int S1 = K1 / BKC, S2 = K2 / BKC, S = S1 + S2;

    float acc[2][8][4];
    #pragma unroll
    for (int t = 0; t < 2; t++)
        #pragma unroll
        for (int n = 0; n < 8; n++)
            #pragma unroll
            for (int j = 0; j < 4; j++) acc[t][n][j] = 0.f;

    auto issue = [&](int s) {
        const __nv_bfloat16 *ah, *al, *bh, *bl; int K, k0;
        if (s < S1) { ah = Ah1; al = Al1; bh = Bh1; bl = Bl1; K = K1; k0 = s * BKC; }
        else        { ah = Ah2; al = Al2; bh = Bh2; bl = Bl2; K = K2; k0 = (s - S1) * BKC; }
        uint32_t sb0 = smb + (s % 3) * STAGE_BYTES;
        #pragma unroll
        for (int t = 0; t < 16; t++) {
            int q = tid + (t << 8);            // 0..4095
            int mat = q >> 10;                 // 0 Ah, 1 Al, 2 Bh, 3 Bl
            int rem = q & 1023;
            int row = rem >> 3;                // 0..127
            int ch  = rem & 7;                 // 16B chunk
            const __nv_bfloat16* g = (mat == 0) ? ah : (mat == 1) ? al : (mat == 2) ? bh : bl;
            int rb = (mat < 2) ? m0 : n0;
            CP_ASYNC16(sb0 + mat * MATB + SW8(row, ch),
                       g + (size_t)(rb + row) * K + k0 + ch * 8);
        }
        CP_COMMIT();
    };

    issue(0);
    if (S > 1) issue(1);
    for (int s = 0; s < S; ++s) {
        if (s + 2 < S) issue(s + 2);
        else CP_COMMIT();
        CP_WAIT2();
        __syncthreads();

        uint32_t sA  = smb + (s % 3) * STAGE_BYTES;
        uint32_t sAl = sA + MATB;
        uint32_t sB  = sA + 2 * MATB;
        uint32_t sBl = sA + 3 * MATB;
        #pragma unroll
        for (int kk4 = 0; kk4 < 4; kk4++) {
            int chb = kk4 * 2;
            uint32_t ahf[2][4], alf[2][4];
            #pragma unroll
            for (int t = 0; t < 2; t++) {
                int row = wm * 32 + t * 16 + ((l >> 3) & 1) * 8 + (l & 7);
                uint32_t ro = SW8(row, chb + (l >> 4));
                ldmx4(ahf[t], sA + ro);
                ldmx4(alf[t], sAl + ro);
            }
            #pragma unroll
            for (int u = 0; u < 4; u++) {
                int row = wn * 64 + u * 16 + (l >> 4) * 8 + (l & 7);
                uint32_t bo = SW8(row, chb + ((l >> 3) & 1));
                uint32_t bhf[4], blf[4];
                ldmx4(bhf, sB + bo);
                ldmx4(blf, sBl + bo);
                #pragma unroll
                for (int t = 0; t < 2; t++) {
                    #pragma unroll
                    for (int h = 0; h < 2; h++) {
                        float* c = acc[t][u * 2 + h];
                        mma_bf16(c, ahf[t], bhf[h * 2], bhf[h * 2 + 1]);
                        mma_bf16(c, ahf[t], blf[h * 2], blf[h * 2 + 1]);
                        mma_bf16(c, alf[t], bhf[h * 2], bhf[h * 2 + 1]);
                    }
                }
            }
        }
        __syncthreads();
    }

    if (mode == 1 && n0 >= QKVW) {
        // fused SwiGLU epilogue: even col = x_ff, odd col = gate (interleaved weights)
        #pragma unroll
        for (int t = 0; t < 2; t++) {
            size_t row = (size_t)(m0 + wm * 32 + t * 16 + (l >> 2));
            #pragma unroll
            for (int n = 0; n < 8; n++) {
                int j = ((n0 - QKVW) + wn * 64 + n * 8 + (l & 3) * 2) >> 1;
                float x0 = acc[t][n][0], gt0 = acc[t][n][1];
                float x1 = acc[t][n][2], gt1 = acc[t][n][3];
                float o0 = x0 * (gt0 / (1.f + __expf(-gt0)));
                float o1 = x1 * (gt1 / (1.f + __expf(-gt1)));
                split2(o0, g_ff_h, g_ff_l, row * FFI + j);
                split2(o1, g_ff_h, g_ff_l, (row + 8) * FFI + j);
            }
        }
    } else {
        #pragma unroll
        for (int t = 0; t < 2; t++) {
            int row = m0 + wm * 32 + t * 16 + (l >> 2);
            #pragma unroll
            for (int n = 0; n < 8; n++) {
                int col = n0 + wn * 64 + n * 8 + (l & 3) * 2;
                *(float2*)(C + (size_t)row * ldc + col)       = make_float2(acc[t][n][0], acc[t][n][1]);
                *(float2*)(C + (size_t)(row + 8) * ldc + col) = make_float2(acc[t][n][2], acc[t][n][3]);
            }
        }
    }
}

// ======================= rope + convert (table-driven) =======================
__global__ void rope_convert_kernel() {
    int r = blockIdx.x;
    int b = r >> 11;
    int n = r & (SEQ - 1);
    const float* row = g_qkv + (size_t)r * QKVW;
    const float2* tab = g_trig + n * 64;
    for (int idx = threadIdx.x; idx < 1152; idx += 256) {
        if (idx < 1024) {            // q: 16 heads x 64 pairs
            int head = idx >> 6, d = idx & 63;
            float2 cs = tab[d];
            float t0 = row[head * DH + d], t1 = row[head * DH + d + 64];
            size_t base = ((size_t)(b * HEADS + head) * SEQ + n) * DH;
            split2(t0 * cs.x - t1 * cs.y, g_q_h, g_q_l, base + d);
            split2(t1 * cs.x + t0 * cs.y, g_q_h, g_q_l, base + d + 64);
        } else if (idx < 1088) {     // k
            int d = idx - 1024;
            float2 cs = tab[d];
            float t0 = row[AINNER + d], t1 = row[AINNER + d + 64];
            size_t base = ((size_t)b * SEQ + n) * DH;
            split2(t0 * cs.x - t1 * cs.y, g_k_h, g_k_l, base + d);
            split2(t1 * cs.x + t0 * cs.y, g_k_h, g_k_l, base + d + 64);
        } else {                     // v
            int d = idx - 1088;
            float t0 = row[AINNER + DH + d], t1 = row[AINNER + DH + d + 64];
            size_t base = ((size_t)b * SEQ + n) * DH;
            split2(t0, g_v_h, g_v_l, base + d);
            split2(t1, g_v_h, g_v_l, base + d + 64);
        }
    }
}

// ======================= tensor-core flash attention (MQA, causal) =======================
// 128-query tile, 8 warps (16 q rows each), 64-key stages double-buffered, swizzled smem.
#define SW16(row, ch) ((uint32_t)((row) * 256 + (((ch) ^ ((row) & 7)) << 4)))
#define QB   (128 * 256)                 // 32768 per Q matrix
#define KB_  (64 * 256)                  // 16384 per KV matrix
#define AT_STG (4 * KB_)                 // 65536 (kh, kl, vh, vl)
#define ATTN_SMEM (2 * QB + 2 * AT_STG)  // 196608

__global__ __launch_bounds__(256, 1)
void attn_mma_kernel() {
    extern __shared__ char asm_sm[];
    uint32_t smb = smem_u32(asm_sm);
    int tid = threadIdx.x, w = tid >> 5, l = tid & 31;
    int qt = gridDim.x - 1 - blockIdx.x;    // long blocks first
    int bh = blockIdx.y;
    int b = bh >> 4, h = bh & 15;

    const __nv_bfloat16* QH = g_q_h + ((size_t)bh * SEQ + qt * 128) * DH;
    const __nv_bfloat16* QL = g_q_l + ((size_t)bh * SEQ + qt * 128) * DH;
    const __nv_bfloat16* KH = g_k_h + (size_t)b * SEQ * DH;
    const __nv_bfloat16* KL = g_k_l + (size_t)b * SEQ * DH;
    const __nv_bfloat16* VH = g_v_h + (size_t)b * SEQ * DH;
    const __nv_bfloat16* VL = g_v_l + (size_t)b * SEQ * DH;

    auto issue_kv = [&](int jt) {
        uint32_t sb0 = smb + 2 * QB + (jt & 1) * AT_STG;
        int rowg = jt * 64;
        #pragma unroll
        for (int t = 0; t < 16; t++) {
            int c = tid + (t << 8);          // 0..4095
            int mat = c >> 10;               // 0 kh, 1 kl, 2 vh, 3 vl
            int rem = c & 1023;
            int row = rem >> 4, ch = rem & 15;
            const __nv_bfloat16* g = (mat == 0) ? KH : (mat == 1) ? KL : (mat == 2) ? VH : VL;
            CP_ASYNC16(sb0 + mat * KB_ + SW16(row, ch),
                       g + (size_t)(rowg + row) * DH + ch * 8);
        }
    };

    // Q load (hi+lo) + first KV stage, one group
    #pragma unroll
    for (int t = 0; t < 16; t++) {
        int c = tid + (t << 8);              // 0..4095
        int mat = c >> 11;                   // 0 Qh, 1 Ql
        int rem = c & 2047;
        int row = rem >> 4, ch = rem & 15;
        const __nv_bfloat16* g = mat ? QL : QH;
        CP_ASYNC16(smb + mat * QB + SW16(row, ch), g + (size_t)row * DH + ch * 8);
    }
    issue_kv(0);
    CP_COMMIT();

    float acc_o[16][4];
    #pragma unroll
    for (int t = 0; t < 16; t++)
        #pragma unroll
        for (int j = 0; j < 4; j++) acc_o[t][j] = 0.f;
    float m_lo = -1e30f, m_hi = -1e30f, l_lo = 0.f, l_hi = 0.f;
    const float scale = 0.08838834764831845f;
    int JT = 2 * qt + 1;
    int qwbase = qt * 128 + w * 16;          // this warp's first q row

    for (int jt = 0; jt <= JT; ++jt) {
        if (jt < JT) { issue_kv(jt + 1); CP_COMMIT(); CP_WAIT1(); }
        else CP_WAIT0();
        __syncthreads();

        if (jt * 64 <= qwbase + 15) {        // stage relevant for this warp
            uint32_t kh = smb + 2 * QB + (jt & 1) * AT_STG;
            uint32_t kl = kh + KB_, vh = kh + 2 * KB_, vl = kh + 3 * KB_;
            bool diag = (jt * 64 + 63 > qwbase);

            // ---- S = Q K^T (3-term) ----
            float s[8][4];
            #pragma unroll
            for (int j = 0; j < 8; j++)
                #pragma unroll
                for (int c = 0; c < 4; c++) s[j][c] = 0.f;
            #pragma unroll
            for (int kk = 0; kk < 8; kk++) {
                int qrow = w * 16 + (l & 15);
                uint32_t qa = SW16(qrow, kk * 2 + (l >> 4));
                uint32_t aH[4], aL[4];
                ldmx4(aH, smb + qa);
                ldmx4(aL, smb + QB + qa);
                #pragma unroll
                for (int j16 = 0; j16 < 4; j16++) {
                    int krow = j16 * 16 + (l & 7) + ((l >= 16) ? 8 : 0);
                    uint32_t ba = SW16(krow, kk * 2 + ((l >> 3) & 1));
                    uint32_t bH[4], bL[4];
                    ldmx4(bH, kh + ba);
                    ldmx4(bL, kl + ba);
                    float* s0 = s[2 * j16];
                    float* s1 = s[2 * j16 + 1];
                    mma_bf16(s0, aH, bH[0], bH[1]);
                    mma_bf16(s0, aH, bL[0], bL[1]);
                    mma_bf16(s0, aL, bH[0], bH[1]);
                    mma_bf16(s1, aH, bH[2], bH[3]);
                    mma_bf16(s1, aH, bL[2], bL[3]);
                    mma_bf16(s1, aL, bH[2], bH[3]);
                }
            }

            // ---- softmax (warp-local) ----
            int r_lo = l >> 2;
            int qg_lo = qwbase + r_lo, qg_hi = qg_lo + 8;
            float mx0 = -1e30f, mx1 = -1e30f;
            #pragma unroll
            for (int j = 0; j < 8; j++) {
                int colg = jt * 64 + j * 8 + (l & 3) * 2;
                #pragma unroll
                for (int c = 0; c < 4; c++) s[j][c] *= scale;
                if (diag) {
                    if (colg     > qg_lo) s[j][0] = -1e30f;
                    if (colg + 1 > qg_lo) s[j][1] = -1e30f;
                    if (colg     > qg_hi) s[j][2] = -1e30f;
                    if (colg + 1 > qg_hi) s[j][3] = -1e30f;
                }
                mx0 = fmaxf(mx0, fmaxf(s[j][0], s[j][1]));
                mx1 = fmaxf(mx1, fmaxf(s[j][2], s[j][3]));
            }
            mx0 = fmaxf(mx0, __shfl_xor_sync(0xffffffffu, mx0, 1));
            mx0 = fmaxf(mx0, __shfl_xor_sync(0xffffffffu, mx0, 2));
            mx1 = fmaxf(mx1, __shfl_xor_sync(0xffffffffu, mx1, 1));
            mx1 = fmaxf(mx1, __shfl_xor_sync(0xffffffffu, mx1, 2));
            float mn0 = fmaxf(m_lo, mx0), mn1 = fmaxf(m_hi, mx1);
            float al0 = __expf(m_lo - mn0), al1 = __expf(m_hi - mn1);
            float su0 = 0.f, su1 = 0.f;
            #pragma unroll
            for (int j = 0; j < 8; j++) {
                s[j][0] = __expf(s[j][0] - mn0);
                s[j][1] = __expf(s[j][1] - mn0);
                s[j][2] = __expf(s[j][2] - mn1);
                s[j][3] = __expf(s[j][3] - mn1);
                su0 += s[j][0] + s[j][1];
                su1 += s[j][2] + s[j][3];
            }
            su0 += __shfl_xor_sync(0xffffffffu, su0, 1);
            su0 += __shfl_xor_sync(0xffffffffu, su0, 2);
            su1 += __shfl_xor_sync(0xffffffffu, su1, 1);
            su1 += __shfl_xor_sync(0xffffffffu, su1, 2);
            l_lo = l_lo * al0 + su0;
            l_hi = l_hi * al1 + su1;
            m_lo = mn0; m_hi = mn1;
            #pragma unroll
            for (int t = 0; t < 16; t++) {
                acc_o[t][0] *= al0; acc_o[t][1] *= al0;
                acc_o[t][2] *= al1; acc_o[t][3] *= al1;
            }

            // ---- O += P V (P split hi/lo; 3-term) ----
            #pragma unroll
            for (int j16 = 0; j16 < 4; j16++) {
                float* t0 = s[2 * j16];
                float* t1 = s[2 * j16 + 1];
                uint32_t ph[4], pl[4];
                #pragma unroll
                for (int q = 0; q < 4; q++) {
                    const float* tt = (q < 2) ? t0 : t1;
                    float p0 = tt[(q & 1) * 2], p1 = tt[(q & 1) * 2 + 1];
                    float h0 = __bfloat162float(__float2bfloat16(p0));
                    float h1 = __bfloat162float(__float2bfloat16(p1));
                    ph[q] = pack_bf16x2(h0, h1);
                    pl[q] = pack_bf16x2(p0 - h0, p1 - h1);
                }
                #pragma unroll
                for (int d16 = 0; d16 < 8; d16++) {
                    int vrow = j16 * 16 + (l & 7) + ((l >> 3) & 1) * 8;
                    uint32_t va = SW16(vrow, d16 * 2 + ((l >= 16) ? 1 : 0));
                    uint32_t bH[4], bL[4];
                    ldmx4t(bH, vh + va);
                    ldmx4t(bL, vl + va);
                    float* o0 = acc_o[2 * d16];
                    float* o1 = acc_o[2 * d16 + 1];
                    mma_bf16(o0, ph, bH[0], bH[1]);
                    mma_bf16(o0, ph, bL[0], bL[1]);
                    mma_bf16(o0, pl, bH[0], bH[1]);
                    mma_bf16(o1, ph, bH[2], bH[3]);
                    mma_bf16(o1, ph, bL[2], bL[3]);
                    mma_bf16(o1, pl, bH[2], bH[3]);
                }
            }
        }
        __syncthreads();
    }

    // ---- epilogue: normalize, write bf16 hi/lo into g_at ----
    float inv0 = 1.0f / l_lo, inv1 = 1.0f / l_hi;
    size_t row0 = (size_t)(b * SEQ + qt * 128 + w * 16 + (l >> 2));
    #pragma unroll
    for (int t = 0; t < 16; t++) {
        int col = h * DH + t * 8 + (l & 3) * 2;
        split2(acc_o[t][0] * inv0, g_at_h, g_at_l, row0 * AINNER + col);
        split2(acc_o[t][1] * inv0, g_at_h, g_at_l, row0 * AINNER + col + 1);
        split2(acc_o[t][2] * inv1, g_at_h, g_at_l, (row0 + 8) * AINNER + col);
        split2(acc_o[t][3] * inv1, g_at_h, g_at_l, (row0 + 8) * AINNER + col + 1);
    }
}

// ======================= launch =======================
extern "C" void kernel_launch(void* const* d_in, const int* in_sizes, int n_in,
                              void* d_out, int out_size) {
    const float* x          = (const float*)d_in[0];
    const float* gamma      = (const float*)d_in[1];
    const float* beta       = (const float*)d_in[2];
    const float* w_fused    = (const float*)d_in[3];
    const float* w_attn_out = (const float*)d_in[4];
    const float* w_ff_out   = (const float*)d_in[5];
    float* out = (float*)d_out;

    void *p;
    float *qkv;
    __nv_bfloat16 *hh, *hl, *wfh, *wfl, *wah, *wal, *woh, *wol, *ath, *atl, *ffh, *ffl;
    cudaGetSymbolAddress(&p, g_qkv); qkv = (float*)p;
    cudaGetSymbolAddress(&p, g_h_hi); hh  = (__nv_bfloat16*)p;
    cudaGetSymbolAddress(&p, g_h_lo); hl  = (__nv_bfloat16*)p;
    cudaGetSymbolAddress(&p, g_wf_h); wfh = (__nv_bfloat16*)p;
    cudaGetSymbolAddress(&p, g_wf_l); wfl = (__nv_bfloat16*)p;
    cudaGetSymbolAddress(&p, g_wa_h); wah = (__nv_bfloat16*)p;
    cudaGetSymbolAddress(&p, g_wa_l); wal = (__nv_bfloat16*)p;
    cudaGetSymbolAddress(&p, g_wo_h); woh = (__nv_bfloat16*)p;
    cudaGetSymbolAddress(&p, g_wo_l); wol = (__nv_bfloat16*)p;
    cudaGetSymbolAddress(&p, g_at_h); ath = (__nv_bfloat16*)p;
    cudaGetSymbolAddress(&p, g_at_l); atl = (__nv_bfloat16*)p;
    cudaGetSymbolAddress(&p, g_ff_h); ffh = (__nv_bfloat16*)p;
    cudaGetSymbolAddress(&p, g_ff_l); ffl = (__nv_bfloat16*)p;

    cudaFuncSetAttribute(gemm_tc, cudaFuncAttributeMaxDynamicSharedMemorySize, GEMM_SMEM);
    cudaFuncSetAttribute(attn_mma_kernel, cudaFuncAttributeMaxDynamicSharedMemorySize, ATTN_SMEM);

    trig_kernel<<<SEQ, 64>>>();
    // weight transpose + split (K-major bf16 hi/lo); w_fused gets ff-interleave remap
    transpose_split<<<dim3(FUSEDW / 32, DIMX / 32), dim3(32, 8)>>>(w_fused, DIMX, FUSEDW, 1, wfh, wfl);
    transpose_split<<<dim3(DIMX / 32, AINNER / 32), dim3(32, 8)>>>(w_attn_out, AINNER, DIMX, 0, wah, wal);
    transpose_split<<<dim3(DIMX / 32, FFI / 32), dim3(32, 8)>>>(w_ff_out, FFI, DIMX, 0, woh, wol);

    ln_split_kernel<<<NROWS, 256>>>(x, gamma, beta);

    // fused projection: qkv (fp32 compact) + SwiGLU'd ff (bf16 hi/lo) in one pass
    gemm_tc<<<dim3(NROWS / 128, FUSEDW / 128), 256, GEMM_SMEM>>>(
        hh, hl, wfh, wfl, DIMX,
        nullptr, nullptr, nullptr, nullptr, 0,
        qkv, QKVW, 1);

    rope_convert_kernel<<<NROWS, 256>>>();

    attn_mma_kernel<<<dim3(SEQ / 128, 2 * HEADS), 256, ATTN_SMEM>>>();

    // out = attn_out @ w_attn_out + ff @ w_ff_out (accumulated in registers)
    gemm_tc<<<dim3(NROWS / 128, DIMX / 128), 256, GEMM_SMEM>>>(
        ath, atl, wah, wal, AINNER,
        ffh, ffl, woh, wol, FFI,
        out, DIMX, 0);
}

// round 6
// speedup vs baseline: 4.5438x; 1.3768x over previous
#include <cuda_runtime.h>
#include <cuda_fp16.h>
#include <math.h>
#include <stdint.h>

#define DIMX    2048
#define HEADS   16
#define DH      128
#define AINNER  2048      // HEADS*DH
#define FFI     8192
#define FUSEDW  18688     // AINNER + 2*DH + 2*FFI
#define QKVW    2304      // AINNER + 2*DH
#define SEQ     2048
#define NROWS   4096      // B*N

// ======================= scratch (static device) =======================
static __device__ float g_qkv[(size_t)NROWS * QKVW];     // 37.7 MB (fp32 q|k|v)
static __device__ float2 g_trig[SEQ * 64];
static __device__ __half g_h_hi[(size_t)NROWS * DIMX],   g_h_lo[(size_t)NROWS * DIMX];
static __device__ __half g_wf[(size_t)FUSEDW * DIMX];            // B single fp16
static __device__ __half g_wa[(size_t)DIMX * AINNER];
static __device__ __half g_wo[(size_t)DIMX * FFI];
static __device__ __half g_at_h[(size_t)NROWS * AINNER], g_at_l[(size_t)NROWS * AINNER];
static __device__ __half g_ff_h[(size_t)NROWS * FFI],    g_ff_l[(size_t)NROWS * FFI];
static __device__ __half g_q_h[(size_t)2 * HEADS * SEQ * DH], g_q_l[(size_t)2 * HEADS * SEQ * DH];
static __device__ __half g_k[(size_t)2 * SEQ * DH];
static __device__ __half g_v[(size_t)2 * SEQ * DH];

__device__ __forceinline__ void split2h(float v, __half* H, __half* L, size_t o) {
    __half h = __float2half_rn(v);
    H[o] = h;
    L[o] = __float2half_rn(v - __half2float(h));
}
__device__ __forceinline__ uint32_t smem_u32(const void* p) {
    uint32_t a;
    asm("{ .reg .u64 t; cvta.to.shared.u64 t, %1; cvt.u32.u64 %0, t; }" : "=r"(a) : "l"(p));
    return a;
}
__device__ __forceinline__ void ldmx4(uint32_t* r, uint32_t addr) {
    asm volatile("ldmatrix.sync.aligned.m8n8.x4.shared.b16 {%0,%1,%2,%3}, [%4];"
                 : "=r"(r[0]), "=r"(r[1]), "=r"(r[2]), "=r"(r[3]) : "r"(addr));
}
__device__ __forceinline__ void ldmx4t(uint32_t* r, uint32_t addr) {
    asm volatile("ldmatrix.sync.aligned.m8n8.x4.trans.shared.b16 {%0,%1,%2,%3}, [%4];"
                 : "=r"(r[0]), "=r"(r[1]), "=r"(r[2]), "=r"(r[3]) : "r"(addr));
}
__device__ __forceinline__ void mma_f16(float* c, const uint32_t* a, uint32_t b0, uint32_t b1) {
    asm volatile(
        "mma.sync.aligned.m16n8k16.row.col.f32.f16.f16.f32 "
        "{%0,%1,%2,%3}, {%4,%5,%6,%7}, {%8,%9}, {%0,%1,%2,%3};"
        : "+f"(c[0]), "+f"(c[1]), "+f"(c[2]), "+f"(c[3])
        : "r"(a[0]), "r"(a[1]), "r"(a[2]), "r"(a[3]), "r"(b0), "r"(b1));
}
__device__ __forceinline__ uint32_t pack_f16x2(float lo, float hi) {
    uint32_t r;
    asm("cvt.rn.f16x2.f32 %0, %1, %2;" : "=r"(r) : "f"(hi), "f"(lo));
    return r;
}
#define CP_ASYNC16(sa, ga) \
    asm volatile("cp.async.cg.shared.global [%0], [%1], 16;" :: "r"(sa), "l"(ga))
#define CP_COMMIT()  asm volatile("cp.async.commit_group;" ::: "memory")
#define CP_WAIT2()   asm volatile("cp.async.wait_group 2;" ::: "memory")
#define CP_WAIT3()   asm volatile("cp.async.wait_group 3;" ::: "memory")

// ======================= trig table =======================
__global__ void trig_kernel() {
    int n = blockIdx.x, d = threadIdx.x;      // 2048 x 64
    double invf = pow(10000.0, -(double)d / 64.0);
    float theta = (float)((double)n * invf);
    g_trig[n * 64 + d] = make_float2((float)cos((double)theta), (float)sin((double)theta));
}

// ======================= LayerNorm -> fp16 split =======================
__global__ void ln_split_kernel(const float* __restrict__ x,
                                const float* __restrict__ gamma,
                                const float* __restrict__ beta) {
    int r = blockIdx.x;
    const float* xr = x + (size_t)r * DIMX;
    float s = 0.f, s2 = 0.f;
    for (int i = threadIdx.x; i < DIMX; i += 256) {
        float v = xr[i]; s += v; s2 += v * v;
    }
    #pragma unroll
    for (int m = 16; m; m >>= 1) {
        s  += __shfl_xor_sync(0xffffffffu, s,  m);
        s2 += __shfl_xor_sync(0xffffffffu, s2, m);
    }
    __shared__ float red0[8], red1[8];
    int w = threadIdx.x >> 5, l = threadIdx.x & 31;
    if (l == 0) { red0[w] = s; red1[w] = s2; }
    __syncthreads();
    __shared__ float smu, srstd;
    if (threadIdx.x == 0) {
        float a = 0.f, b2 = 0.f;
        #pragma unroll
        for (int i = 0; i < 8; i++) { a += red0[i]; b2 += red1[i]; }
        float mu  = a / DIMX;
        float var = b2 / DIMX - mu * mu;
        smu = mu; srstd = 1.0f / sqrtf(var + 1e-5f);
    }
    __syncthreads();
    float mu = smu, rstd = srstd;
    for (int i = threadIdx.x; i < DIMX; i += 256) {
        float v = (xr[i] - mu) * rstd * gamma[i] + beta[i];
        split2h(v, g_h_hi, g_h_lo, (size_t)r * DIMX + i);
    }
}

// ======================= transpose to K-major fp16 (optional ff interleave) ============
__global__ void transpose_half(const float* __restrict__ W, int K, int N, int remap,
                               __half* __restrict__ T) {
    __shared__ float t[32][33];
    int n0 = blockIdx.x * 32, k0 = blockIdx.y * 32;
    int tx = threadIdx.x, ty = threadIdx.y;
    for (int j = ty; j < 32; j += 8) {
        int oc = n0 + tx;
        int sc = oc;
        if (remap && oc >= QKVW) {
            int lf = oc - QKVW;
            sc = QKVW + (lf >> 1) + ((lf & 1) ? FFI : 0);
        }
        t[j][tx] = W[(size_t)(k0 + j) * N + sc];
    }
    __syncthreads();
    for (int j = ty; j < 32; j += 8)
        T[(size_t)(n0 + j) * K + k0 + tx] = __float2half_rn(t[tx][j]);
}

// ======================= mma.sync dual-phase GEMM (fp16 2-term, BK=64, 4-stage) ========
#define BKC 64
#define MATB (128 * 128)               // bytes per matrix tile
#define STAGE_BYTES (3 * MATB)         // 49152 (Ah, Al, B)
#define GEMM_SMEM (4 * STAGE_BYTES)    // 196608
#define SW8(row, ch) ((uint32_t)((row) * 128 + (((ch) ^ ((row) & 7)) << 4)))

__global__ __launch_bounds__(256, 1)
void gemm_tc(const __half* __restrict__ Ah1, const __half* __restrict__ Al1,
             const __half* __restrict__ B1, int K1,
             const __half* __restrict__ Ah2, const __half* __restrict__ Al2,
             const __half* __restrict__ B2, int K2,
             float* __restrict__ C, int ldc, int mode) {
    extern __shared__ char smem[];
    uint32_t smb = smem_u32(smem);
    int tid = threadIdx.x;
    int w = tid >> 5, l = tid & 31;
    int wm = w & 3, wn = w >> 2;
    int m0 = blockIdx.x * 128;
    int n0 = blockIdx.y * 128;
    int S1 = K1 / BKC, S2 = K2 / BKC, S = S1 + S2;

    float acc[2][8][4];
    #pragma unroll
    for (int t = 0; t < 2; t++)
        #pragma unroll
        for (int n = 0; n < 8; n++)
            #pragma unroll
            for (int j = 0; j < 4; j++) acc[t][n][j] = 0.f;

    auto issue = [&](int s) {
        const __half *ah, *al, *bb; int K, k0;
        if (s < S1) { ah = Ah1; al = Al1; bb = B1; K = K1; k0 = s * BKC; }
        else        { ah = Ah2; al = Al2; bb = B2; K = K2; k0 = (s - S1) * BKC; }
        uint32_t sb0 = smb + (s & 3) * STAGE_BYTES;
        #pragma unroll
        for (int t = 0; t < 12; t++) {
            int q = tid + (t << 8);            // 0..3071
            int mat = q >> 10;                 // 0 Ah, 1 Al, 2 B
            int rem = q & 1023;
            int row = rem >> 3;
            int ch  = rem & 7;
            const __half* g = (mat == 0) ? ah : (mat == 1) ? al : bb;
            int rb = (mat < 2) ? m0 : n0;
            CP_ASYNC16(sb0 + mat * MATB + SW8(row, ch),
                       g + (size_t)(rb + row) * K + k0 + ch * 8);
        }
        CP_COMMIT();
    };

    issue(0);
    if (S > 1) issue(1);
    if (S > 2) issue(2);
    for (int s = 0; s < S; ++s) {
        if (s + 3 < S) issue(s + 3);
        else CP_COMMIT();
        CP_WAIT3();
        __syncthreads();

        uint32_t sA  = smb + (s & 3) * STAGE_BYTES;
        uint32_t sAl = sA + MATB;
        uint32_t sB  = sA + 2 * MATB;
        #pragma unroll
        for (int kk4 = 0; kk4 < 4; kk4++) {
            int chb = kk4 * 2;
            uint32_t ahf[2][4], alf[2][4];
            #pragma unroll
            for (int t = 0; t < 2; t++) {
                int row = wm * 32 + t * 16 + ((l >> 3) & 1) * 8 + (l & 7);
                uint32_t ro = SW8(row, chb + (l >> 4));
                ldmx4(ahf[t], sA + ro);
                ldmx4(alf[t], sAl + ro);
            }
            #pragma unroll
            for (int u = 0; u < 4; u++) {
                int row = wn * 64 + u * 16 + (l >> 4) * 8 + (l & 7);
                uint32_t bo = SW8(row, chb + ((l >> 3) & 1));
                uint32_t bf[4];
                ldmx4(bf, sB + bo);
                #pragma unroll
                for (int t = 0; t < 2; t++) {
                    #pragma unroll
                    for (int h = 0; h < 2; h++) {
                        float* c = acc[t][u * 2 + h];
                        mma_f16(c, ahf[t], bf[h * 2], bf[h * 2 + 1]);
                        mma_f16(c, alf[t], bf[h * 2], bf[h * 2 + 1]);
                    }
                }
            }
        }
        __syncthreads();
    }

    if (mode == 1 && n0 >= QKVW) {
        // fused SwiGLU epilogue: even col = x_ff, odd col = gate (interleaved weights)
        #pragma unroll
        for (int t = 0; t < 2; t++) {
            size_t row = (size_t)(m0 + wm * 32 + t * 16 + (l >> 2));
            #pragma unroll
            for (int n = 0; n < 8; n++) {
                int j = ((n0 - QKVW) + wn * 64 + n * 8 + (l & 3) * 2) >> 1;
                float x0 = acc[t][n][0], gt0 = acc[t][n][1];
                float x1 = acc[t][n][2], gt1 = acc[t][n][3];
                float o0 = x0 * (gt0 / (1.f + __expf(-gt0)));
                float o1 = x1 * (gt1 / (1.f + __expf(-gt1)));
                split2h(o0, g_ff_h, g_ff_l, row * FFI + j);
                split2h(o1, g_ff_h, g_ff_l, (row + 8) * FFI + j);
            }
        }
    } else {
        #pragma unroll
        for (int t = 0; t < 2; t++) {
            int row = m0 + wm * 32 + t * 16 + (l >> 2);
            #pragma unroll
            for (int n = 0; n < 8; n++) {
                int col = n0 + wn * 64 + n * 8 + (l & 3) * 2;
                *(float2*)(C + (size_t)row * ldc + col)       = make_float2(acc[t][n][0], acc[t][n][1]);
                *(float2*)(C + (size_t)(row + 8) * ldc + col) = make_float2(acc[t][n][2], acc[t][n][3]);
            }
        }
    }
}

// ======================= rope + convert (table-driven) =======================
__global__ void rope_convert_kernel() {
    int r = blockIdx.x;
    int b = r >> 11;
    int n = r & (SEQ - 1);
    const float* row = g_qkv + (size_t)r * QKVW;
    const float2* tab = g_trig + n * 64;
    for (int idx = threadIdx.x; idx < 1152; idx += 256) {
        if (idx < 1024) {            // q: 16 heads x 64 pairs (fp16 split)
            int head = idx >> 6, d = idx & 63;
            float2 cs = tab[d];
            float t0 = row[head * DH + d], t1 = row[head * DH + d + 64];
            size_t base = ((size_t)(b * HEADS + head) * SEQ + n) * DH;
            split2h(t0 * cs.x - t1 * cs.y, g_q_h, g_q_l, base + d);
            split2h(t1 * cs.x + t0 * cs.y, g_q_h, g_q_l, base + d + 64);
        } else if (idx < 1088) {     // k (single fp16)
            int d = idx - 1024;
            float2 cs = tab[d];
            float t0 = row[AINNER + d], t1 = row[AINNER + d + 64];
            size_t base = ((size_t)b * SEQ + n) * DH;
            g_k[base + d]      = __float2half_rn(t0 * cs.x - t1 * cs.y);
            g_k[base + d + 64] = __float2half_rn(t1 * cs.x + t0 * cs.y);
        } else {                     // v (single fp16)
            int d = idx - 1088;
            float t0 = row[AINNER + DH + d], t1 = row[AINNER + DH + d + 64];
            size_t base = ((size_t)b * SEQ + n) * DH;
            g_v[base + d]      = __float2half_rn(t0);
            g_v[base + d + 64] = __float2half_rn(t1);
        }
    }
}

// ======================= tensor-core flash attention (fp16 2-term, 3-stage KV) =========
#define SW16(row, ch) ((uint32_t)((row) * 256 + (((ch) ^ ((row) & 7)) << 4)))
#define QB   (128 * 256)                 // 32768 per Q matrix
#define KB_  (64 * 256)                  // 16384 per KV matrix
#define AT_STG (2 * KB_)                 // 32768 (k, v)
#define ATTN_SMEM (2 * QB + 3 * AT_STG)  // 163840

__global__ __launch_bounds__(256, 1)
void attn_mma_kernel() {
    extern __shared__ char asm_sm[];
    uint32_t smb = smem_u32(asm_sm);
    int tid = threadIdx.x, w = tid >> 5, l = tid & 31;
    int qt = gridDim.x - 1 - blockIdx.x;    // long blocks first
    int bh = blockIdx.y;
    int b = bh >> 4, h = bh & 15;

    const __half* QH = g_q_h + ((size_t)bh * SEQ + qt * 128) * DH;
    const __half* QL = g_q_l + ((size_t)bh * SEQ + qt * 128) * DH;
    const __half* KK = g_k + (size_t)b * SEQ * DH;
    const __half* VV = g_v + (size_t)b * SEQ * DH;

    auto issue_kv = [&](int jt) {
        uint32_t sb0 = smb + 2 * QB + (jt % 3) * AT_STG;
        int rowg = jt * 64;
        #pragma unroll
        for (int t = 0; t < 8; t++) {
            int c = tid + (t << 8);          // 0..2047
            int mat = c >> 10;               // 0 k, 1 v
            int rem = c & 1023;
            int row = rem >> 4, ch = rem & 15;
            const __half* g = mat ? VV : KK;
            CP_ASYNC16(sb0 + mat * KB_ + SW16(row, ch),
                       g + (size_t)(rowg + row) * DH + ch * 8);
        }
    };

    // Q load (hi+lo) + first KV stage in group 0, second KV stage group 1
    #pragma unroll
    for (int t = 0; t < 16; t++) {
        int c = tid + (t << 8);              // 0..4095
        int mat = c >> 11;                   // 0 Qh, 1 Ql
        int rem = c & 2047;
        int row = rem >> 4, ch = rem & 15;
        const __half* g = mat ? QL : QH;
        CP_ASYNC16(smb + mat * QB + SW16(row, ch), g + (size_t)row * DH + ch * 8);
    }
    issue_kv(0);
    CP_COMMIT();
    int JT = 2 * qt + 1;
    issue_kv(1);                              // JT >= 1 always
    CP_COMMIT();

    float acc_o[16][4];
    #pragma unroll
    for (int t = 0; t < 16; t++)
        #pragma unroll
        for (int j = 0; j < 4; j++) acc_o[t][j] = 0.f;
    float m_lo = -1e30f, m_hi = -1e30f, l_lo = 0.f, l_hi = 0.f;
    const float scale = 0.08838834764831845f;
    int qwbase = qt * 128 + w * 16;          // this warp's first q row

    for (int jt = 0; jt <= JT; ++jt) {
        if (jt + 2 <= JT) issue_kv(jt + 2);
        CP_COMMIT();
        CP_WAIT2();
        __syncthreads();

        if (jt * 64 <= qwbase + 15) {        // stage relevant for this warp
            uint32_t kz = smb + 2 * QB + (jt % 3) * AT_STG;
            uint32_t vz = kz + KB_;
            bool diag = (jt * 64 + 63 > qwbase);

            // ---- S = Q K^T (2-term: Qh*K + Ql*K) ----
            float s[8][4];
            #pragma unroll
            for (int j = 0; j < 8; j++)
                #pragma unroll
                for (int c = 0; c < 4; c++) s[j][c] = 0.f;
            #pragma unroll
            for (int kk = 0; kk < 8; kk++) {
                int qrow = w * 16 + (l & 15);
                uint32_t qa = SW16(qrow, kk * 2 + (l >> 4));
                uint32_t aH[4], aL[4];
                ldmx4(aH, smb + qa);
                ldmx4(aL, smb + QB + qa);
                #pragma unroll
                for (int j16 = 0; j16 < 4; j16++) {
                    int krow = j16 * 16 + (l & 7) + ((l >= 16) ? 8 : 0);
                    uint32_t ba = SW16(krow, kk * 2 + ((l >> 3) & 1));
                    uint32_t bK[4];
                    ldmx4(bK, kz + ba);
                    float* s0 = s[2 * j16];
                    float* s1 = s[2 * j16 + 1];
                    mma_f16(s0, aH, bK[0], bK[1]);
                    mma_f16(s0, aL, bK[0], bK[1]);
                    mma_f16(s1, aH, bK[2], bK[3]);
                    mma_f16(s1, aL, bK[2], bK[3]);
                }
            }

            // ---- softmax (warp-local) ----
            int r_lo = l >> 2;
            int qg_lo = qwbase + r_lo, qg_hi = qg_lo + 8;
            float mx0 = -1e30f, mx1 = -1e30f;
            #pragma unroll
            for (int j = 0; j < 8; j++) {
                int colg = jt * 64 + j * 8 + (l & 3) * 2;
                #pragma unroll
                for (int c = 0; c < 4; c++) s[j][c] *= scale;
                if (diag) {
                    if (colg     > qg_lo) s[j][0] = -1e30f;
                    if (colg + 1 > qg_lo) s[j][1] = -1e30f;
                    if (colg     > qg_hi) s[j][2] = -1e30f;
                    if (colg + 1 > qg_hi) s[j][3] = -1e30f;
                }
                mx0 = fmaxf(mx0, fmaxf(s[j][0], s[j][1]));
                mx1 = fmaxf(mx1, fmaxf(s[j][2], s[j][3]));
            }
            mx0 = fmaxf(mx0, __shfl_xor_sync(0xffffffffu, mx0, 1));
            mx0 = fmaxf(mx0, __shfl_xor_sync(0xffffffffu, mx0, 2));
            mx1 = fmaxf(mx1, __shfl_xor_sync(0xffffffffu, mx1, 1));
            mx1 = fmaxf(mx1, __shfl_xor_sync(0xffffffffu, mx1, 2));
            float mn0 = fmaxf(m_lo, mx0), mn1 = fmaxf(m_hi, mx1);
            float al0 = __expf(m_lo - mn0), al1 = __expf(m_hi - mn1);
            float su0 = 0.f, su1 = 0.f;
            #pragma unroll
            for (int j = 0; j < 8; j++) {
                s[j][0] = __expf(s[j][0] - mn0);
                s[j][1] = __expf(s[j][1] - mn0);
                s[j][2] = __expf(s[j][2] - mn1);
                s[j][3] = __expf(s[j][3] - mn1);
                su0 += s[j][0] + s[j][1];
                su1 += s[j][2] + s[j][3];
            }
            su0 += __shfl_xor_sync(0xffffffffu, su0, 1);
            su0 += __shfl_xor_sync(0xffffffffu, su0, 2);
            su1 += __shfl_xor_sync(0xffffffffu, su1, 1);
            su1 += __shfl_xor_sync(0xffffffffu, su1, 2);
            l_lo = l_lo * al0 + su0;
            l_hi = l_hi * al1 + su1;
            m_lo = mn0; m_hi = mn1;
            #pragma unroll
            for (int t = 0; t < 16; t++) {
                acc_o[t][0] *= al0; acc_o[t][1] *= al0;
                acc_o[t][2] *= al1; acc_o[t][3] *= al1;
            }

            // ---- O += P V (P split hi/lo fp16; 2-term) ----
            #pragma unroll
            for (int j16 = 0; j16 < 4; j16++) {
                float* t0 = s[2 * j16];
                float* t1 = s[2 * j16 + 1];
                uint32_t ph[4], pl[4];
                #pragma unroll
                for (int q = 0; q < 4; q++) {
                    const float* tt = (q < 2) ? t0 : t1;
                    float p0 = tt[(q & 1) * 2], p1 = tt[(q & 1) * 2 + 1];
                    float h0 = __half2float(__float2half_rn(p0));
                    float h1 = __half2float(__float2half_rn(p1));
                    ph[q] = pack_f16x2(h0, h1);
                    pl[q] = pack_f16x2(p0 - h0, p1 - h1);
                }
                #pragma unroll
                for (int d16 = 0; d16 < 8; d16++) {
                    int vrow = j16 * 16 + (l & 7) + ((l >> 3) & 1) * 8;
                    uint32_t va = SW16(vrow, d16 * 2 + ((l >= 16) ? 1 : 0));
                    uint32_t bV[4];
                    ldmx4t(bV, vz + va);
                    float* o0 = acc_o[2 * d16];
                    float* o1 = acc_o[2 * d16 + 1];
                    mma_f16(o0, ph, bV[0], bV[1]);
                    mma_f16(o0, pl, bV[0], bV[1]);
                    mma_f16(o1, ph, bV[2], bV[3]);
                    mma_f16(o1, pl, bV[2], bV[3]);
                }
            }
        }
        __syncthreads();
    }

    // ---- epilogue: normalize, write fp16 hi/lo into g_at ----
    float inv0 = 1.0f / l_lo, inv1 = 1.0f / l_hi;
    size_t row0 = (size_t)(b * SEQ + qt * 128 + w * 16 + (l >> 2));
    #pragma unroll
    for (int t = 0; t < 16; t++) {
        int col = h * DH + t * 8 + (l & 3) * 2;
        split2h(acc_o[t][0] * inv0, g_at_h, g_at_l, row0 * AINNER + col);
        split2h(acc_o[t][1] * inv0, g_at_h, g_at_l, row0 * AINNER + col + 1);
        split2h(acc_o[t][2] * inv1, g_at_h, g_at_l, (row0 + 8) * AINNER + col);
        split2h(acc_o[t][3] * inv1, g_at_h, g_at_l, (row0 + 8) * AINNER + col + 1);
    }
}

// ======================= launch =======================
extern "C" void kernel_launch(void* const* d_in, const int* in_sizes, int n_in,
                              void* d_out, int out_size) {
    const float* x          = (const float*)d_in[0];
    const float* gamma      = (const float*)d_in[1];
    const float* beta       = (const float*)d_in[2];
    const float* w_fused    = (const float*)d_in[3];
    const float* w_attn_out = (const float*)d_in[4];
    const float* w_ff_out   = (const float*)d_in[5];
    float* out = (float*)d_out;

    void *p;
    float *qkv;
    __half *hh, *hl, *wf, *wa, *wo, *ath, *atl, *ffh, *ffl;
    cudaGetSymbolAddress(&p, g_qkv);  qkv = (float*)p;
    cudaGetSymbolAddress(&p, g_h_hi); hh  = (__half*)p;
    cudaGetSymbolAddress(&p, g_h_lo); hl  = (__half*)p;
    cudaGetSymbolAddress(&p, g_wf);   wf  = (__half*)p;
    cudaGetSymbolAddress(&p, g_wa);   wa  = (__half*)p;
    cudaGetSymbolAddress(&p, g_wo);   wo  = (__half*)p;
    cudaGetSymbolAddress(&p, g_at_h); ath = (__half*)p;
    cudaGetSymbolAddress(&p, g_at_l); atl = (__half*)p;
    cudaGetSymbolAddress(&p, g_ff_h); ffh = (__half*)p;
    cudaGetSymbolAddress(&p, g_ff_l); ffl = (__half*)p;

    cudaFuncSetAttribute(gemm_tc, cudaFuncAttributeMaxDynamicSharedMemorySize, GEMM_SMEM);
    cudaFuncSetAttribute(attn_mma_kernel, cudaFuncAttributeMaxDynamicSharedMemorySize, ATTN_SMEM);

    trig_kernel<<<SEQ, 64>>>();
    // weight transpose to K-major fp16; w_fused gets ff-interleave remap
    transpose_half<<<dim3(FUSEDW / 32, DIMX / 32), dim3(32, 8)>>>(w_fused, DIMX, FUSEDW, 1, wf);
    transpose_half<<<dim3(DIMX / 32, AINNER / 32), dim3(32, 8)>>>(w_attn_out, AINNER, DIMX, 0, wa);
    transpose_half<<<dim3(DIMX / 32, FFI / 32), dim3(32, 8)>>>(w_ff_out, FFI, DIMX, 0, wo);

    ln_split_kernel<<<NROWS, 256>>>(x, gamma, beta);

    // fused projection: qkv (fp32 compact) + SwiGLU'd ff (fp16 hi/lo) in one pass
    gemm_tc<<<dim3(NROWS / 128, FUSEDW / 128), 256, GEMM_SMEM>>>(
        hh, hl, wf, DIMX,
        nullptr, nullptr, nullptr, 0,
        qkv, QKVW, 1);

    rope_convert_kernel<<<NROWS, 256>>>();

    attn_mma_kernel<<<dim3(SEQ / 128, 2 * HEADS), 256, ATTN_SMEM>>>();

    // out = attn_out @ w_attn_out + ff @ w_ff_out (accumulated in registers)
    gemm_tc<<<dim3(NROWS / 128, DIMX / 128), 256, GEMM_SMEM>>>(
        ath, atl, wa, AINNER,
        ffh, ffl, wo, FFI,
        out, DIMX, 0);
}

// round 9
// speedup vs baseline: 4.8130x; 1.0592x over previous
#include <cuda_runtime.h>
#include <cuda_fp16.h>
#include <math.h>
#include <stdint.h>

#define DIMX    2048
#define HEADS   16
#define DH      128
#define AINNER  2048      // HEADS*DH
#define FFI     8192
#define FUSEDW  18688     // AINNER + 2*DH + 2*FFI
#define QKVW    2304      // AINNER + 2*DH
#define SEQ     2048
#define NROWS   4096      // B*N

// ======================= scratch (static device) =======================
static __device__ float g_qkv[(size_t)NROWS * QKVW];     // 37.7 MB (fp32 q|k|v)
static __device__ float2 g_trig[SEQ * 64];
static __device__ __half g_h_hi[(size_t)NROWS * DIMX],   g_h_lo[(size_t)NROWS * DIMX];
static __device__ __half g_wf[(size_t)FUSEDW * DIMX];            // B single fp16
static __device__ __half g_wa[(size_t)DIMX * AINNER];
static __device__ __half g_wo[(size_t)DIMX * FFI];
static __device__ __half g_at_h[(size_t)NROWS * AINNER], g_at_l[(size_t)NROWS * AINNER];
static __device__ __half g_ff_h[(size_t)NROWS * FFI],    g_ff_l[(size_t)NROWS * FFI];
static __device__ __half g_q_h[(size_t)2 * HEADS * SEQ * DH], g_q_l[(size_t)2 * HEADS * SEQ * DH];
static __device__ __half g_k[(size_t)2 * SEQ * DH];
static __device__ __half g_v[(size_t)2 * SEQ * DH];

__device__ __forceinline__ void split2h(float v, __half* H, __half* L, size_t o) {
    __half h = __float2half_rn(v);
    H[o] = h;
    L[o] = __float2half_rn(v - __half2float(h));
}
__device__ __forceinline__ uint32_t smem_u32(const void* p) {
    uint32_t a;
    asm("{ .reg .u64 t; cvta.to.shared.u64 t, %1; cvt.u32.u64 %0, t; }" : "=r"(a) : "l"(p));
    return a;
}
__device__ __forceinline__ void ldmx4(uint32_t* r, uint32_t addr) {
    asm volatile("ldmatrix.sync.aligned.m8n8.x4.shared.b16 {%0,%1,%2,%3}, [%4];"
                 : "=r"(r[0]), "=r"(r[1]), "=r"(r[2]), "=r"(r[3]) : "r"(addr));
}
__device__ __forceinline__ void ldmx4t(uint32_t* r, uint32_t addr) {
    asm volatile("ldmatrix.sync.aligned.m8n8.x4.trans.shared.b16 {%0,%1,%2,%3}, [%4];"
                 : "=r"(r[0]), "=r"(r[1]), "=r"(r[2]), "=r"(r[3]) : "r"(addr));
}
__device__ __forceinline__ void mma_f16(float* c, const uint32_t* a, uint32_t b0, uint32_t b1) {
    asm volatile(
        "mma.sync.aligned.m16n8k16.row.col.f32.f16.f16.f32 "
        "{%0,%1,%2,%3}, {%4,%5,%6,%7}, {%8,%9}, {%0,%1,%2,%3};"
        : "+f"(c[0]), "+f"(c[1]), "+f"(c[2]), "+f"(c[3])
        : "r"(a[0]), "r"(a[1]), "r"(a[2]), "r"(a[3]), "r"(b0), "r"(b1));
}
__device__ __forceinline__ uint32_t pack_f16x2(float lo, float hi) {
    uint32_t r;
    asm("cvt.rn.f16x2.f32 %0, %1, %2;" : "=r"(r) : "f"(hi), "f"(lo));
    return r;
}
#define CP_ASYNC16(sa, ga) \
    asm volatile("cp.async.cg.shared.global [%0], [%1], 16;" :: "r"(sa), "l"(ga))
#define CP_COMMIT()  asm volatile("cp.async.commit_group;" ::: "memory")
#define CP_WAIT2()   asm volatile("cp.async.wait_group 2;" ::: "memory")

// ======================= trig table =======================
__global__ void trig_kernel() {
    int n = blockIdx.x, d = threadIdx.x;      // 2048 x 64
    double invf = pow(10000.0, -(double)d / 64.0);
    float theta = (float)((double)n * invf);
    g_trig[n * 64 + d] = make_float2((float)cos((double)theta), (float)sin((double)theta));
}

// ======================= LayerNorm -> fp16 split =======================
__global__ void ln_split_kernel(const float* __restrict__ x,
                                const float* __restrict__ gamma,
                                const float* __restrict__ beta) {
    int r = blockIdx.x;
    const float* xr = x + (size_t)r * DIMX;
    float s = 0.f, s2 = 0.f;
    for (int i = threadIdx.x; i < DIMX; i += 256) {
        float v = xr[i]; s += v; s2 += v * v;
    }
    #pragma unroll
    for (int m = 16; m; m >>= 1) {
        s  += __shfl_xor_sync(0xffffffffu, s,  m);
        s2 += __shfl_xor_sync(0xffffffffu, s2, m);
    }
    __shared__ float red0[8], red1[8];
    int w = threadIdx.x >> 5, l = threadIdx.x & 31;
    if (l == 0) { red0[w] = s; red1[w] = s2; }
    __syncthreads();
    __shared__ float smu, srstd;
    if (threadIdx.x == 0) {
        float a = 0.f, b2 = 0.f;
        #pragma unroll
        for (int i = 0; i < 8; i++) { a += red0[i]; b2 += red1[i]; }
        float mu  = a / DIMX;
        float var = b2 / DIMX - mu * mu;
        smu = mu; srstd = 1.0f / sqrtf(var + 1e-5f);
    }
    __syncthreads();
    float mu = smu, rstd = srstd;
    for (int i = threadIdx.x; i < DIMX; i += 256) {
        float v = (xr[i] - mu) * rstd * gamma[i] + beta[i];
        split2h(v, g_h_hi, g_h_lo, (size_t)r * DIMX + i);
    }
}

// ======================= transpose to K-major fp16 (optional ff interleave) ============
__global__ void transpose_half(const float* __restrict__ W, int K, int N, int remap,
                               __half* __restrict__ T) {
    __shared__ float t[32][33];
    int n0 = blockIdx.x * 32, k0 = blockIdx.y * 32;
    int tx = threadIdx.x, ty = threadIdx.y;
    for (int j = ty; j < 32; j += 8) {
        int oc = n0 + tx;
        int sc = oc;
        if (remap && oc >= QKVW) {
            int lf = oc - QKVW;
            sc = QKVW + (lf >> 1) + ((lf & 1) ? FFI : 0);
        }
        t[j][tx] = W[(size_t)(k0 + j) * N + sc];
    }
    __syncthreads();
    for (int j = ty; j < 32; j += 8)
        T[(size_t)(n0 + j) * K + k0 + tx] = __float2half_rn(t[tx][j]);
}

// ======================= mma.sync dual-phase GEMM =======================
// Block tile 128x256, 8 warps (warp tile 64x64), BK=64, fp16 2-term A split,
// 3 smem buffers with prefetch depth 2 (read s%3 while s+1, s+2 in flight).
#define BKC 64
#define MATB_A 16384                   // 128 rows x 128B
#define MATB_B 32768                   // 256 rows x 128B
#define STAGE_BYTES (2 * MATB_A + MATB_B)   // 65536
#define GEMM_SMEM (3 * STAGE_BYTES)         // 196608
#define SW8(row, ch) ((uint32_t)((row) * 128 + (((ch) ^ ((row) & 7)) << 4)))

__global__ __launch_bounds__(256, 1)
void gemm_tc(const __half* __restrict__ Ah1, const __half* __restrict__ Al1,
             const __half* __restrict__ B1, int K1,
             const __half* __restrict__ Ah2, const __half* __restrict__ Al2,
             const __half* __restrict__ B2, int K2,
             float* __restrict__ C, int ldc, int mode) {
    extern __shared__ char smem[];
    uint32_t smb = smem_u32(smem);
    int tid = threadIdx.x;
    int w = tid >> 5, l = tid & 31;
    int wm = w & 1, wn = w >> 1;               // 2 x 4 warp grid, 64x64 per warp
    int m0 = blockIdx.x * 128;
    int n0 = blockIdx.y * 256;
    int S1 = K1 / BKC, S2 = K2 / BKC, S = S1 + S2;

    float acc[4][8][4];
    #pragma unroll
    for (int mf = 0; mf < 4; mf++)
        #pragma unroll
        for (int n = 0; n < 8; n++)
            #pragma unroll
            for (int j = 0; j < 4; j++) acc[mf][n][j] = 0.f;

    auto issue = [&](int s) {
        const __half *ah, *al, *bb; int K, k0;
        if (s < S1) { ah = Ah1; al = Al1; bb = B1; K = K1; k0 = s * BKC; }
        else        { ah = Ah2; al = Al2; bb = B2; K = K2; k0 = (s - S1) * BKC; }
        uint32_t sb0 = smb + (s % 3) * STAGE_BYTES;
        #pragma unroll
        for (int t = 0; t < 16; t++) {
            int q = tid + (t << 8);            // 0..4095
            if (q < 2048) {                    // A hi/lo: 2 x 128 rows x 8 ch
                int mat = q >> 10;
                int rem = q & 1023;
                int row = rem >> 3, ch = rem & 7;
                const __half* g = mat ? al : ah;
                CP_ASYNC16(sb0 + mat * MATB_A + SW8(row, ch),
                           g + (size_t)(m0 + row) * K + k0 + ch * 8);
            } else {                           // B: 256 rows x 8 ch
                int rem = q - 2048;
                int row = rem >> 3, ch = rem & 7;
                CP_ASYNC16(sb0 + 2 * MATB_A + SW8(row, ch),
                           bb + (size_t)(n0 + row) * K + k0 + ch * 8);
            }
        }
        CP_COMMIT();
    };

    issue(0);
    if (S > 1) issue(1);
    for (int s = 0; s < S; ++s) {
        if (s + 2 < S) issue(s + 2);
        else CP_COMMIT();                      // empty group keeps wait count uniform
        CP_WAIT2();
        __syncthreads();

        uint32_t sA  = smb + (s % 3) * STAGE_BYTES;
        uint32_t sAl = sA + MATB_A;
        uint32_t sB  = sA + 2 * MATB_A;
        #pragma unroll
        for (int kk4 = 0; kk4 < 4; kk4++) {
            int chb = kk4 * 2;
            uint32_t aH[4][4], aL[4][4];
            #pragma unroll
            for (int mf = 0; mf < 4; mf++) {
                int row = wm * 64 + mf * 16 + ((l >> 3) & 1) * 8 + (l & 7);
                uint32_t ro = SW8(row, chb + (l >> 4));
                ldmx4(aH[mf], sA + ro);
                ldmx4(aL[mf], sAl + ro);
            }
            #pragma unroll
            for (int u = 0; u < 4; u++) {
                int row = wn * 64 + u * 16 + (l >> 4) * 8 + (l & 7);
                uint32_t bo = SW8(row, chb + ((l >> 3) & 1));
                uint32_t bf[4];
                ldmx4(bf, sB + bo);
                // hi pass: 8 independent accumulators, then lo pass (RAW distance 8)
                #pragma unroll
                for (int mf = 0; mf < 4; mf++)
                    #pragma unroll
                    for (int h = 0; h < 2; h++)
                        mma_f16(acc[mf][u * 2 + h], aH[mf], bf[h * 2], bf[h * 2 + 1]);
                #pragma unroll
                for (int mf = 0; mf < 4; mf++)
                    #pragma unroll
                    for (int h = 0; h < 2; h++)
                        mma_f16(acc[mf][u * 2 + h], aL[mf], bf[h * 2], bf[h * 2 + 1]);
            }
        }
        __syncthreads();
    }

    if (mode == 1 && n0 >= QKVW) {
        // fused SwiGLU epilogue: even col = x_ff, odd col = gate (interleaved weights)
        #pragma unroll
        for (int mf = 0; mf < 4; mf++) {
            size_t row = (size_t)(m0 + wm * 64 + mf * 16 + (l >> 2));
            #pragma unroll
            for (int n = 0; n < 8; n++) {
                int j = ((n0 - QKVW) + wn * 64 + n * 8 + (l & 3) * 2) >> 1;
                float x0 = acc[mf][n][0], gt0 = acc[mf][n][1];
                float x1 = acc[mf][n][2], gt1 = acc[mf][n][3];
                float o0 = x0 * (gt0 / (1.f + __expf(-gt0)));
                float o1 = x1 * (gt1 / (1.f + __expf(-gt1)));
                split2h(o0, g_ff_h, g_ff_l, row * FFI + j);
                split2h(o1, g_ff_h, g_ff_l, (row + 8) * FFI + j);
            }
        }
    } else {
        #pragma unroll
        for (int mf = 0; mf < 4; mf++) {
            int row = m0 + wm * 64 + mf * 16 + (l >> 2);
            #pragma unroll
            for (int n = 0; n < 8; n++) {
                int col = n0 + wn * 64 + n * 8 + (l & 3) * 2;
                *(float2*)(C + (size_t)row * ldc + col)       = make_float2(acc[mf][n][0], acc[mf][n][1]);
                *(float2*)(C + (size_t)(row + 8) * ldc + col) = make_float2(acc[mf][n][2], acc[mf][n][3]);
            }
        }
    }
}

// ======================= rope + convert (table-driven) =======================
__global__ void rope_convert_kernel() {
    int r = blockIdx.x;
    int b = r >> 11;
    int n = r & (SEQ - 1);
    const float* row = g_qkv + (size_t)r * QKVW;
    const float2* tab = g_trig + n * 64;
    for (int idx = threadIdx.x; idx < 1152; idx += 256) {
        if (idx < 1024) {            // q: 16 heads x 64 pairs (fp16 split)
            int head = idx >> 6, d = idx & 63;
            float2 cs = tab[d];
            float t0 = row[head * DH + d], t1 = row[head * DH + d + 64];
            size_t base = ((size_t)(b * HEADS + head) * SEQ + n) * DH;
            split2h(t0 * cs.x - t1 * cs.y, g_q_h, g_q_l, base + d);
            split2h(t1 * cs.x + t0 * cs.y, g_q_h, g_q_l, base + d + 64);
        } else if (idx < 1088) {     // k (single fp16)
            int d = idx - 1024;
            float2 cs = tab[d];
            float t0 = row[AINNER + d], t1 = row[AINNER + d + 64];
            size_t base = ((size_t)b * SEQ + n) * DH;
            g_k[base + d]      = __float2half_rn(t0 * cs.x - t1 * cs.y);
            g_k[base + d + 64] = __float2half_rn(t1 * cs.x + t0 * cs.y);
        } else {                     // v (single fp16)
            int d = idx - 1088;
            float t0 = row[AINNER + DH + d], t1 = row[AINNER + DH + d + 64];
            size_t base = ((size_t)b * SEQ + n) * DH;
            g_v[base + d]      = __float2half_rn(t0);
            g_v[base + d + 64] = __float2half_rn(t1);
        }
    }
}

// ======================= tensor-core flash attention (fp16 2-term, 3-stage KV) =========
#define SW16(row, ch) ((uint32_t)((row) * 256 + (((ch) ^ ((row) & 7)) << 4)))
#define QB   (128 * 256)                 // 32768 per Q matrix
#define KB_  (64 * 256)                  // 16384 per KV matrix
#define AT_STG (2 * KB_)                 // 32768 (k, v)
#define ATTN_SMEM (2 * QB + 3 * AT_STG)  // 163840

__global__ __launch_bounds__(256, 1)
void attn_mma_kernel() {
    extern __shared__ char asm_sm[];
    uint32_t smb = smem_u32(asm_sm);
    int tid = threadIdx.x, w = tid >> 5, l = tid & 31;
    int qt = gridDim.x - 1 - blockIdx.x;    // long blocks first
    int bh = blockIdx.y;
    int b = bh >> 4, h = bh & 15;

    const __half* QH = g_q_h + ((size_t)bh * SEQ + qt * 128) * DH;
    const __half* QL = g_q_l + ((size_t)bh * SEQ + qt * 128) * DH;
    const __half* KK = g_k + (size_t)b * SEQ * DH;
    const __half* VV = g_v + (size_t)b * SEQ * DH;

    auto issue_kv = [&](int jt) {
        uint32_t sb0 = smb + 2 * QB + (jt % 3) * AT_STG;
        int rowg = jt * 64;
        #pragma unroll
        for (int t = 0; t < 8; t++) {
            int c = tid + (t << 8);          // 0..2047
            int mat = c >> 10;               // 0 k, 1 v
            int rem = c & 1023;
            int row = rem >> 4, ch = rem & 15;
            const __half* g = mat ? VV : KK;
            CP_ASYNC16(sb0 + mat * KB_ + SW16(row, ch),
                       g + (size_t)(rowg + row) * DH + ch * 8);
        }
    };

    // Q load (hi+lo) + first KV stage in group 0, second KV stage group 1
    #pragma unroll
    for (int t = 0; t < 16; t++) {
        int c = tid + (t << 8);              // 0..4095
        int mat = c >> 11;                   // 0 Qh, 1 Ql
        int rem = c & 2047;
        int row = rem >> 4, ch = rem & 15;
        const __half* g = mat ? QL : QH;
        CP_ASYNC16(smb + mat * QB + SW16(row, ch), g + (size_t)row * DH + ch * 8);
    }
    issue_kv(0);
    CP_COMMIT();
    int JT = 2 * qt + 1;
    issue_kv(1);                              // JT >= 1 always
    CP_COMMIT();

    float acc_o[16][4];
    #pragma unroll
    for (int t = 0; t < 16; t++)
        #pragma unroll
        for (int j = 0; j < 4; j++) acc_o[t][j] = 0.f;
    float m_lo = -1e30f, m_hi = -1e30f, l_lo = 0.f, l_hi = 0.f;
    const float scale = 0.08838834764831845f;
    int qwbase = qt * 128 + w * 16;          // this warp's first q row

    for (int jt = 0; jt <= JT; ++jt) {
        if (jt + 2 <= JT) issue_kv(jt + 2);
        CP_COMMIT();
        CP_WAIT2();
        __syncthreads();

        if (jt * 64 <= qwbase + 15) {        // stage relevant for this warp
            uint32_t kz = smb + 2 * QB + (jt % 3) * AT_STG;
            uint32_t vz = kz + KB_;
            bool diag = (jt * 64 + 63 > qwbase);

            // ---- S = Q K^T (2-term: Qh*K + Ql*K) ----
            float s[8][4];
            #pragma unroll
            for (int j = 0; j < 8; j++)
                #pragma unroll
                for (int c = 0; c < 4; c++) s[j][c] = 0.f;
            #pragma unroll
            for (int kk = 0; kk < 8; kk++) {
                int qrow = w * 16 + (l & 15);
                uint32_t qa = SW16(qrow, kk * 2 + (l >> 4));
                uint32_t aH[4], aL[4];
                ldmx4(aH, smb + qa);
                ldmx4(aL, smb + QB + qa);
                #pragma unroll
                for (int j16 = 0; j16 < 4; j16++) {
                    int krow = j16 * 16 + (l & 7) + ((l >= 16) ? 8 : 0);
                    uint32_t ba = SW16(krow, kk * 2 + ((l >> 3) & 1));
                    uint32_t bK[4];
                    ldmx4(bK, kz + ba);
                    float* s0 = s[2 * j16];
                    float* s1 = s[2 * j16 + 1];
                    mma_f16(s0, aH, bK[0], bK[1]);
                    mma_f16(s0, aL, bK[0], bK[1]);
                    mma_f16(s1, aH, bK[2], bK[3]);
                    mma_f16(s1, aL, bK[2], bK[3]);
                }
            }

            // ---- softmax (warp-local) ----
            int r_lo = l >> 2;
            int qg_lo = qwbase + r_lo, qg_hi = qg_lo + 8;
            float mx0 = -1e30f, mx1 = -1e30f;
            #pragma unroll
            for (int j = 0; j < 8; j++) {
                int colg = jt * 64 + j * 8 + (l & 3) * 2;
                #pragma unroll
                for (int c = 0; c < 4; c++) s[j][c] *= scale;
                if (diag) {
                    if (colg     > qg_lo) s[j][0] = -1e30f;
                    if (colg + 1 > qg_lo) s[j][1] = -1e30f;
                    if (colg     > qg_hi) s[j][2] = -1e30f;
                    if (colg + 1 > qg_hi) s[j][3] = -1e30f;
                }
                mx0 = fmaxf(mx0, fmaxf(s[j][0], s[j][1]));
                mx1 = fmaxf(mx1, fmaxf(s[j][2], s[j][3]));
            }
            mx0 = fmaxf(mx0, __shfl_xor_sync(0xffffffffu, mx0, 1));
            mx0 = fmaxf(mx0, __shfl_xor_sync(0xffffffffu, mx0, 2));
            mx1 = fmaxf(mx1, __shfl_xor_sync(0xffffffffu, mx1, 1));
            mx1 = fmaxf(mx1, __shfl_xor_sync(0xffffffffu, mx1, 2));
            float mn0 = fmaxf(m_lo, mx0), mn1 = fmaxf(m_hi, mx1);
            float al0 = __expf(m_lo - mn0), al1 = __expf(m_hi - mn1);
            float su0 = 0.f, su1 = 0.f;
            #pragma unroll
            for (int j = 0; j < 8; j++) {
                s[j][0] = __expf(s[j][0] - mn0);
                s[j][1] = __expf(s[j][1] - mn0);
                s[j][2] = __expf(s[j][2] - mn1);
                s[j][3] = __expf(s[j][3] - mn1);
                su0 += s[j][0] + s[j][1];
                su1 += s[j][2] + s[j][3];
            }
            su0 += __shfl_xor_sync(0xffffffffu, su0, 1);
            su0 += __shfl_xor_sync(0xffffffffu, su0, 2);
            su1 += __shfl_xor_sync(0xffffffffu, su1, 1);
            su1 += __shfl_xor_sync(0xffffffffu, su1, 2);
            l_lo = l_lo * al0 + su0;
            l_hi = l_hi * al1 + su1;
            m_lo = mn0; m_hi = mn1;
            #pragma unroll
            for (int t = 0; t < 16; t++) {
                acc_o[t][0] *= al0; acc_o[t][1] *= al0;
                acc_o[t][2] *= al1; acc_o[t][3] *= al1;
            }

            // ---- O += P V (P split hi/lo fp16; 2-term) ----
            #pragma unroll
            for (int j16 = 0; j16 < 4; j16++) {
                float* t0 = s[2 * j16];
                float* t1 = s[2 * j16 + 1];
                uint32_t ph[4], pl[4];
                #pragma unroll
                for (int q = 0; q < 4; q++) {
                    const float* tt = (q < 2) ? t0 : t1;
                    float p0 = tt[(q & 1) * 2], p1 = tt[(q & 1) * 2 + 1];
                    float h0 = __half2float(__float2half_rn(p0));
                    float h1 = __half2float(__float2half_rn(p1));
                    ph[q] = pack_f16x2(h0, h1);
                    pl[q] = pack_f16x2(p0 - h0, p1 - h1);
                }
                #pragma unroll
                for (int d16 = 0; d16 < 8; d16++) {
                    int vrow = j16 * 16 + (l & 7) + ((l >> 3) & 1) * 8;
                    uint32_t va = SW16(vrow, d16 * 2 + ((l >= 16) ? 1 : 0));
                    uint32_t bV[4];
                    ldmx4t(bV, vz + va);
                    float* o0 = acc_o[2 * d16];
                    float* o1 = acc_o[2 * d16 + 1];
                    mma_f16(o0, ph, bV[0], bV[1]);
                    mma_f16(o0, pl, bV[0], bV[1]);
                    mma_f16(o1, ph, bV[2], bV[3]);
                    mma_f16(o1, pl, bV[2], bV[3]);
                }
            }
        }
        __syncthreads();
    }

    // ---- epilogue: normalize, write fp16 hi/lo into g_at ----
    float inv0 = 1.0f / l_lo, inv1 = 1.0f / l_hi;
    size_t row0 = (size_t)(b * SEQ + qt * 128 + w * 16 + (l >> 2));
    #pragma unroll
    for (int t = 0; t < 16; t++) {
        int col = h * DH + t * 8 + (l & 3) * 2;
        split2h(acc_o[t][0] * inv0, g_at_h, g_at_l, row0 * AINNER + col);
        split2h(acc_o[t][1] * inv0, g_at_h, g_at_l, row0 * AINNER + col + 1);
        split2h(acc_o[t][2] * inv1, g_at_h, g_at_l, (row0 + 8) * AINNER + col);
        split2h(acc_o[t][3] * inv1, g_at_h, g_at_l, (row0 + 8) * AINNER + col + 1);
    }
}

// ======================= launch =======================
extern "C" void kernel_launch(void* const* d_in, const int* in_sizes, int n_in,
                              void* d_out, int out_size) {
    const float* x          = (const float*)d_in[0];
    const float* gamma      = (const float*)d_in[1];
    const float* beta       = (const float*)d_in[2];
    const float* w_fused    = (const float*)d_in[3];
    const float* w_attn_out = (const float*)d_in[4];
    const float* w_ff_out   = (const float*)d_in[5];
    float* out = (float*)d_out;

    void *p;
    float *qkv;
    __half *hh, *hl, *wf, *wa, *wo, *ath, *atl, *ffh, *ffl;
    cudaGetSymbolAddress(&p, g_qkv);  qkv = (float*)p;
    cudaGetSymbolAddress(&p, g_h_hi); hh  = (__half*)p;
    cudaGetSymbolAddress(&p, g_h_lo); hl  = (__half*)p;
    cudaGetSymbolAddress(&p, g_wf);   wf  = (__half*)p;
    cudaGetSymbolAddress(&p, g_wa);   wa  = (__half*)p;
    cudaGetSymbolAddress(&p, g_wo);   wo  = (__half*)p;
    cudaGetSymbolAddress(&p, g_at_h); ath = (__half*)p;
    cudaGetSymbolAddress(&p, g_at_l); atl = (__half*)p;
    cudaGetSymbolAddress(&p, g_ff_h); ffh = (__half*)p;
    cudaGetSymbolAddress(&p, g_ff_l); ffl = (__half*)p;

    cudaFuncSetAttribute(gemm_tc, cudaFuncAttributeMaxDynamicSharedMemorySize, GEMM_SMEM);
    cudaFuncSetAttribute(attn_mma_kernel, cudaFuncAttributeMaxDynamicSharedMemorySize, ATTN_SMEM);

    trig_kernel<<<SEQ, 64>>>();
    // weight transpose to K-major fp16; w_fused gets ff-interleave remap
    transpose_half<<<dim3(FUSEDW / 32, DIMX / 32), dim3(32, 8)>>>(w_fused, DIMX, FUSEDW, 1, wf);
    transpose_half<<<dim3(DIMX / 32, AINNER / 32), dim3(32, 8)>>>(w_attn_out, AINNER, DIMX, 0, wa);
    transpose_half<<<dim3(DIMX / 32, FFI / 32), dim3(32, 8)>>>(w_ff_out, FFI, DIMX, 0, wo);

    ln_split_kernel<<<NROWS, 256>>>(x, gamma, beta);

    // fused projection: qkv (fp32 compact) + SwiGLU'd ff (fp16 hi/lo) in one pass
    gemm_tc<<<dim3(NROWS / 128, FUSEDW / 256), 256, GEMM_SMEM>>>(
        hh, hl, wf, DIMX,
        nullptr, nullptr, nullptr, 0,
        qkv, QKVW, 1);

    rope_convert_kernel<<<NROWS, 256>>>();

    attn_mma_kernel<<<dim3(SEQ / 128, 2 * HEADS), 256, ATTN_SMEM>>>();

    // out = attn_out @ w_attn_out + ff @ w_ff_out (accumulated in registers)
    gemm_tc<<<dim3(NROWS / 128, DIMX / 256), 256, GEMM_SMEM>>>(
        ath, atl, wa, AINNER,
        ffh, ffl, wo, FFI,
        out, DIMX, 0);
}